// round 4
// baseline (speedup 1.0000x reference)
#include <cuda_runtime.h>
#include <cuda_bf16.h>
#include <cstdint>

// ---------------------------------------------------------------------------
// Problem constants
// ---------------------------------------------------------------------------
#define EMAX 262144
#define DD   128
#define DAA  64

// Scratch (device globals; no allocations allowed)
__device__ float g_buf0[(size_t)EMAX * DD];
__device__ float g_buf1[(size_t)EMAX * DD];
__device__ float g_xdown[(size_t)EMAX * DAA];
__device__ float g_agg[(size_t)EMAX * DAA];
__device__ float g_wrbf[6 * DD];

// ---------------------------------------------------------------------------
// PTX helpers (plain sm_103-legal: ldmatrix + mma.sync HMMA path)
// ---------------------------------------------------------------------------
__device__ __forceinline__ uint32_t smem_u32(const void* p) {
    uint32_t a;
    asm("{ .reg .u64 t; cvta.to.shared.u64 t, %1; cvt.u32.u64 %0, t; }"
        : "=r"(a) : "l"(p));
    return a;
}

__device__ __forceinline__ void ldsm_x4(uint32_t& r0, uint32_t& r1,
                                        uint32_t& r2, uint32_t& r3, uint32_t addr) {
    asm volatile("ldmatrix.sync.aligned.m8n8.x4.shared.b16 {%0,%1,%2,%3}, [%4];"
                 : "=r"(r0), "=r"(r1), "=r"(r2), "=r"(r3) : "r"(addr));
}

__device__ __forceinline__ void mma_bf16(float* c, const uint32_t* a,
                                         uint32_t b0, uint32_t b1) {
    asm volatile(
        "mma.sync.aligned.m16n8k16.row.col.f32.bf16.bf16.f32 "
        "{%0,%1,%2,%3}, {%4,%5,%6,%7}, {%8,%9}, {%0,%1,%2,%3};"
        : "+f"(c[0]), "+f"(c[1]), "+f"(c[2]), "+f"(c[3])
        : "r"(a[0]), "r"(a[1]), "r"(a[2]), "r"(a[3]), "r"(b0), "r"(b1));
}

__device__ __forceinline__ uint32_t pk_bf2(__nv_bfloat16 a, __nv_bfloat16 b) {
    __nv_bfloat162 t(a, b);
    return *reinterpret_cast<uint32_t*>(&t);
}

__device__ __forceinline__ float swishf(float x) {
    return x * (1.0f / (1.0f + __expf(-x)));
}
__device__ __forceinline__ void red_add_v4(float* p, float4 v) {
    asm volatile("red.global.add.v4.f32 [%0], {%1, %2, %3, %4};"
                 :: "l"(p), "f"(v.x), "f"(v.y), "f"(v.z), "f"(v.w) : "memory");
}

// ---------------------------------------------------------------------------
// Utility kernels
// ---------------------------------------------------------------------------
__global__ void zero_kernel(float* __restrict__ p, int n) {
    int i = blockIdx.x * blockDim.x + threadIdx.x;
    if (i < n) p[i] = 0.0f;
}

__global__ void wrbf_kernel(const float* __restrict__ W1, const float* __restrict__ W2,
                            float* __restrict__ out) {
    int c = threadIdx.x;
    #pragma unroll
    for (int r = 0; r < 6; r++) {
        float s = 0.f;
        #pragma unroll
        for (int j = 0; j < 8; j++) s += W1[r * 8 + j] * W2[j * DD + c];
        out[r * DD + c] = s;
    }
}

// ---------------------------------------------------------------------------
// HMMA bf16-split GEMM: Y = [res +] swish(X@W [+ b]) [* rbf_gate]
//   X: [nrows, NI] fp32, W: [NI, NO] fp32 row-major, Y: [nrows, NO] fp32.
//   A and B^T live in smem as bf16 hi/lo (padded rows, conflict-free ldmatrix).
//   3 MMA passes (hh, hl, lh) accumulate in fp32 registers.
//   BM=128 rows/CTA, 256 threads (8 warps).
// ---------------------------------------------------------------------------
template <int NI, int NO, bool GATE, bool BIAS, bool RES>
__global__ __launch_bounds__(256)
void gemm_mma(const float* __restrict__ X, const float* __restrict__ W,
              const float* __restrict__ bias, const float* __restrict__ res,
              const float* __restrict__ rbf, const float* __restrict__ Wrbf,
              float* __restrict__ Y, int nrows) {
    extern __shared__ char smem[];
    constexpr int STR = NI * 2 + 16;       // bytes per smem row (pad kills conflicts)
    constexpr int ASZ = 128 * STR;         // per A copy
    constexpr int BSZ = NO * STR;          // per B copy
    constexpr int OFF_GATE = 0;
    constexpr int OFF_A_HI = 4096;
    constexpr int OFF_A_LO = OFF_A_HI + ASZ;
    constexpr int OFF_B_HI = OFF_A_LO + ASZ;
    constexpr int OFF_B_LO = OFF_B_HI + BSZ;

    const uint32_t sb = smem_u32(smem);
    const int tid = threadIdx.x;
    const int row0 = blockIdx.x * 128;

    if (GATE) {
        for (int i = tid; i < 6 * NO; i += 256)
            *(float*)(smem + OFF_GATE + 4 * i) = Wrbf[i];
    }

    // B^T: W[k][n] -> smem row n, col k (bf16 hi/lo)
    for (int i = tid; i < NI * NO; i += 256) {
        int k = i / NO, n = i % NO;
        float v = W[i];
        __nv_bfloat16 h = __float2bfloat16(v);
        __nv_bfloat16 l = __float2bfloat16(v - __bfloat162float(h));
        uint32_t off = (uint32_t)(n * STR + k * 2);
        *(__nv_bfloat16*)(smem + OFF_B_HI + off) = h;
        *(__nv_bfloat16*)(smem + OFF_B_LO + off) = l;
    }

    // A: X tile [128, NI] (coalesced float4 loads, bf16 hi/lo)
    {
        constexpr int RV = NI / 4;
        for (int i = tid; i < 128 * RV; i += 256) {
            int r = i / RV, c4 = (i % RV) * 4;
            int rr = row0 + r; if (rr >= nrows) rr = nrows - 1;
            float4 v = *(const float4*)&X[(size_t)rr * NI + c4];
            __nv_bfloat16 h0 = __float2bfloat16(v.x), h1 = __float2bfloat16(v.y);
            __nv_bfloat16 h2 = __float2bfloat16(v.z), h3 = __float2bfloat16(v.w);
            __nv_bfloat16 l0 = __float2bfloat16(v.x - __bfloat162float(h0));
            __nv_bfloat16 l1 = __float2bfloat16(v.y - __bfloat162float(h1));
            __nv_bfloat16 l2 = __float2bfloat16(v.z - __bfloat162float(h2));
            __nv_bfloat16 l3 = __float2bfloat16(v.w - __bfloat162float(h3));
            uint32_t off = (uint32_t)(r * STR + c4 * 2);
            uint2 hv; hv.x = pk_bf2(h0, h1); hv.y = pk_bf2(h2, h3);
            uint2 lv; lv.x = pk_bf2(l0, l1); lv.y = pk_bf2(l2, l3);
            *(uint2*)(smem + OFF_A_HI + off) = hv;
            *(uint2*)(smem + OFF_A_LO + off) = lv;
        }
    }
    __syncthreads();

    // ---- MMA main loop -----------------------------------------------------
    constexpr int WPM = (NO == 128) ? 4 : 8;   // warps along M
    constexpr int WM  = 128 / WPM;             // 32 or 16
    constexpr int MI  = WM / 16;               // 2 or 1
    constexpr int NJ  = 8;                     // 64 cols / 8

    const int w = tid >> 5, lane = tid & 31;
    const int wm0 = (w % WPM) * WM;
    const int wn0 = (w / WPM) * 64;
    const int lr = lane & 15;                  // ldmatrix row within 16
    const int lk = (lane >> 4) * 8;            // ldmatrix k offset (0/8)

    float acc[MI][NJ][4];
    #pragma unroll
    for (int mi = 0; mi < MI; mi++)
        #pragma unroll
        for (int nj = 0; nj < NJ; nj++)
            #pragma unroll
            for (int q = 0; q < 4; q++) acc[mi][nj][q] = 0.f;

    #pragma unroll
    for (int pass = 0; pass < 3; pass++) {
        const uint32_t abase = sb + (pass == 2 ? OFF_A_LO : OFF_A_HI);
        const uint32_t bbase = sb + (pass == 1 ? OFF_B_LO : OFF_B_HI);
        #pragma unroll
        for (int k0 = 0; k0 < NI; k0 += 16) {
            uint32_t a[MI][4];
            #pragma unroll
            for (int mi = 0; mi < MI; mi++)
                ldsm_x4(a[mi][0], a[mi][1], a[mi][2], a[mi][3],
                        abase + (uint32_t)((wm0 + mi * 16 + lr) * STR + (k0 + lk) * 2));
            uint32_t b[4][4];
            #pragma unroll
            for (int g = 0; g < 4; g++)
                ldsm_x4(b[g][0], b[g][1], b[g][2], b[g][3],
                        bbase + (uint32_t)((wn0 + g * 16 + lr) * STR + (k0 + lk) * 2));
            #pragma unroll
            for (int mi = 0; mi < MI; mi++)
                #pragma unroll
                for (int nj = 0; nj < NJ; nj++) {
                    int g = nj >> 1, o = nj & 1;
                    mma_bf16(acc[mi][nj], a[mi], b[g][o], b[g][o + 2]);
                }
        }
    }

    // ---- Epilogue: stage C through smem for coalesced global stores --------
    __syncthreads();
    float* stage = (float*)(smem + OFF_A_HI);
    constexpr int SSTR = NO + 4;
    {
        const int sr = lane >> 2, sc = (lane & 3) * 2;
        #pragma unroll
        for (int mi = 0; mi < MI; mi++)
            #pragma unroll
            for (int nj = 0; nj < NJ; nj++) {
                int r = wm0 + mi * 16 + sr;
                int c = wn0 + nj * 8 + sc;
                *(float2*)&stage[r * SSTR + c] =
                    make_float2(acc[mi][nj][0], acc[mi][nj][1]);
                *(float2*)&stage[(r + 8) * SSTR + c] =
                    make_float2(acc[mi][nj][2], acc[mi][nj][3]);
            }
    }
    __syncthreads();

    constexpr int RV = NO / 4;
    for (int idx = tid; idx < 128 * RV; idx += 256) {
        int r = idx / RV, c = (idx % RV) * 4;
        int row = row0 + r;
        if (row >= nrows) continue;
        float4 v = *(float4*)&stage[r * SSTR + c];
        float o[4] = {v.x, v.y, v.z, v.w};
        if (BIAS) {
            float4 bv = *(const float4*)&bias[c];
            o[0] += bv.x; o[1] += bv.y; o[2] += bv.z; o[3] += bv.w;
        }
        #pragma unroll
        for (int q = 0; q < 4; q++) o[q] = swishf(o[q]);
        if (GATE) {
            float rv6[6];
            #pragma unroll
            for (int j = 0; j < 6; j++) rv6[j] = rbf[(size_t)row * 6 + j];
            #pragma unroll
            for (int q = 0; q < 4; q++) {
                float g = 0.f;
                #pragma unroll
                for (int j = 0; j < 6; j++)
                    g += rv6[j] * *(const float*)(smem + OFF_GATE + 4 * (j * NO + c + q));
                o[q] *= g;
            }
        }
        if (RES) {
            float4 rsv = *(const float4*)&res[(size_t)row * NO + c];
            o[0] += rsv.x; o[1] += rsv.y; o[2] += rsv.z; o[3] += rsv.w;
        }
        *(float4*)&Y[(size_t)row * NO + c] = make_float4(o[0], o[1], o[2], o[3]);
    }
}

// ---------------------------------------------------------------------------
// Triplet kernel: gather -> sbf gate -> vector atomic scatter-sum
// ---------------------------------------------------------------------------
#define TPB_TRIP 64
__global__ __launch_bounds__(256)
void triplet_kernel(const float* __restrict__ sbf, const int* __restrict__ expand,
                    const int* __restrict__ reduce, const float* __restrict__ Wsbf1,
                    const float* __restrict__ Wsbf2, const float* __restrict__ xdown,
                    float* __restrict__ agg, int Ttot) {
    __shared__ float s_sbf[TPB_TRIP * 42];
    __shared__ float s_h[TPB_TRIP * 9];
    __shared__ float s_w1[42 * 8];
    __shared__ float s_w2[8 * 64];
    __shared__ int   s_ekj[TPB_TRIP];
    __shared__ int   s_eji[TPB_TRIP];

    const int tid  = threadIdx.x;
    const int base = blockIdx.x * TPB_TRIP;
    const int n_t  = min(TPB_TRIP, Ttot - base);

    for (int i = tid; i < 42 * 8; i += 256) s_w1[i] = Wsbf1[i];
    for (int i = tid; i < 8 * 64; i += 256) s_w2[i] = Wsbf2[i];
    for (int i = tid; i < n_t * 42; i += 256) s_sbf[i] = sbf[(size_t)base * 42 + i];
    if (tid < n_t) {
        s_ekj[tid] = expand[base + tid];
        s_eji[tid] = reduce[base + tid];
    }
    __syncthreads();

    for (int wi = tid; wi < n_t * 8; wi += 256) {
        int i = wi >> 3, j = wi & 7;
        float s = 0.f;
        #pragma unroll
        for (int k = 0; k < 42; k++) s += s_sbf[i * 42 + k] * s_w1[k * 8 + j];
        s_h[i * 9 + j] = s;
    }
    __syncthreads();

    const int trip = tid >> 2;
    const int c0   = (tid & 3) * 16;
    if (trip < n_t) {
        float h[8];
        #pragma unroll
        for (int j = 0; j < 8; j++) h[j] = s_h[trip * 9 + j];
        const int ekj = s_ekj[trip];
        const int eji = s_eji[trip];
        const float4* xp = (const float4*)(xdown + (size_t)ekj * DAA + c0);
        float* ap = agg + (size_t)eji * DAA + c0;
        #pragma unroll
        for (int q = 0; q < 4; q++) {
            float4 x = xp[q];
            int cb = c0 + q * 4;
            float g0 = 0.f, g1 = 0.f, g2 = 0.f, g3 = 0.f;
            #pragma unroll
            for (int j = 0; j < 8; j++) {
                float4 wv = *(const float4*)&s_w2[j * 64 + cb];
                float hj = h[j];
                g0 += hj * wv.x; g1 += hj * wv.y; g2 += hj * wv.z; g3 += hj * wv.w;
            }
            red_add_v4(ap + q * 4, make_float4(x.x * g0, x.y * g1, x.z * g2, x.w * g3));
        }
    }
}

// ---------------------------------------------------------------------------
// Host launcher
// ---------------------------------------------------------------------------
static inline int smem_bytes(int NI, int NO) {
    int STR = NI * 2 + 16;
    return 4096 + 2 * 128 * STR + 2 * NO * STR;
}

extern "C" void kernel_launch(void* const* d_in, const int* in_sizes, int n_in,
                              void* d_out, int out_size) {
    const float* m_input = (const float*)d_in[0];
    const float* rbf     = (const float*)d_in[1];
    const float* sbf     = (const float*)d_in[2];
    const int*   expand  = (const int*)d_in[3];
    const int*   reduce  = (const int*)d_in[4];
    const float* W_kj    = (const float*)d_in[5];
    const float* b_kj    = (const float*)d_in[6];
    const float* W_rbf1  = (const float*)d_in[7];
    const float* W_rbf2  = (const float*)d_in[8];
    const float* W_sbf1  = (const float*)d_in[9];
    const float* W_sbf2  = (const float*)d_in[10];
    const float* W_down  = (const float*)d_in[11];
    const float* W_up    = (const float*)d_in[12];
    const float* W_ji    = (const float*)d_in[13];
    const float* b_ji    = (const float*)d_in[14];
    const float* W_res_b = (const float*)d_in[15];
    const float* b_res_b = (const float*)d_in[16];
    const float* W_final = (const float*)d_in[17];
    const float* b_final = (const float*)d_in[18];
    const float* W_res_a = (const float*)d_in[19];
    const float* b_res_a = (const float*)d_in[20];
    float* out = (float*)d_out;

    const int E = in_sizes[0] / DD;
    const int T = in_sizes[3];

    float *buf0, *buf1, *xdown, *agg, *wrbf;
    cudaGetSymbolAddress((void**)&buf0, g_buf0);
    cudaGetSymbolAddress((void**)&buf1, g_buf1);
    cudaGetSymbolAddress((void**)&xdown, g_xdown);
    cudaGetSymbolAddress((void**)&agg, g_agg);
    cudaGetSymbolAddress((void**)&wrbf, g_wrbf);

    const int S_128_128 = smem_bytes(128, 128);
    const int S_128_64  = smem_bytes(128, 64);
    const int S_64_128  = smem_bytes(64, 128);
    cudaFuncSetAttribute(gemm_mma<128, 128, true,  true,  false>,
                         cudaFuncAttributeMaxDynamicSharedMemorySize, S_128_128);
    cudaFuncSetAttribute(gemm_mma<128, 64,  false, false, false>,
                         cudaFuncAttributeMaxDynamicSharedMemorySize, S_128_64);
    cudaFuncSetAttribute(gemm_mma<64,  128, false, false, false>,
                         cudaFuncAttributeMaxDynamicSharedMemorySize, S_64_128);
    cudaFuncSetAttribute(gemm_mma<128, 128, false, true,  false>,
                         cudaFuncAttributeMaxDynamicSharedMemorySize, S_128_128);
    cudaFuncSetAttribute(gemm_mma<128, 128, false, true,  true>,
                         cudaFuncAttributeMaxDynamicSharedMemorySize, S_128_128);

    const int gblocks = (E + 127) / 128;

    // 0) zero agg
    {
        int n = E * DAA;
        zero_kernel<<<(n + 255) / 256, 256>>>(agg, n);
    }
    // 1) fuse rbf projection weights
    wrbf_kernel<<<1, 128>>>(W_rbf1, W_rbf2, wrbf);

    // 2) buf0 = swish(m_input@W_kj + b_kj) * ((rbf@Wrbf1)@Wrbf2)
    gemm_mma<128, 128, true, true, false><<<gblocks, 256, S_128_128>>>(
        m_input, W_kj, b_kj, nullptr, rbf, wrbf, buf0, E);
    // 3) xdown = swish(buf0 @ W_down)
    gemm_mma<128, 64, false, false, false><<<gblocks, 256, S_128_64>>>(
        buf0, W_down, nullptr, nullptr, nullptr, nullptr, xdown, E);
    // 4) triplet gather/gate/scatter-sum
    triplet_kernel<<<(T + TPB_TRIP - 1) / TPB_TRIP, 256>>>(
        sbf, expand, reduce, W_sbf1, W_sbf2, xdown, agg, T);
    // 5) buf1 = swish(agg @ W_up)
    gemm_mma<64, 128, false, false, false><<<gblocks, 256, S_64_128>>>(
        agg, W_up, nullptr, nullptr, nullptr, nullptr, buf1, E);
    // 6) buf0 = swish(m_input@W_ji + b_ji) + buf1
    gemm_mma<128, 128, false, true, true><<<gblocks, 256, S_128_128>>>(
        m_input, W_ji, b_ji, buf1, nullptr, nullptr, buf0, E);
    // 7) buf1 = swish(buf0 @ Wb[0] + bb[0])
    gemm_mma<128, 128, false, true, false><<<gblocks, 256, S_128_128>>>(
        buf0, W_res_b, b_res_b, nullptr, nullptr, nullptr, buf1, E);
    // 8) buf1 = buf0 + swish(buf1 @ Wb[1] + bb[1])
    gemm_mma<128, 128, false, true, true><<<gblocks, 256, S_128_128>>>(
        buf1, W_res_b + DD * DD, b_res_b + DD, buf0, nullptr, nullptr, buf1, E);
    // 9) buf0 = swish(buf1 @ W_final + b_final) + m_input
    gemm_mma<128, 128, false, true, true><<<gblocks, 256, S_128_128>>>(
        buf1, W_final, b_final, m_input, nullptr, nullptr, buf0, E);
    // 10) buf1 = swish(buf0 @ Wa[0,0] + ba[0,0])
    gemm_mma<128, 128, false, true, false><<<gblocks, 256, S_128_128>>>(
        buf0, W_res_a, b_res_a, nullptr, nullptr, nullptr, buf1, E);
    // 11) buf1 = buf0 + swish(buf1 @ Wa[0,1] + ba[0,1])
    gemm_mma<128, 128, false, true, true><<<gblocks, 256, S_128_128>>>(
        buf1, W_res_a + DD * DD, b_res_a + DD, buf0, nullptr, nullptr, buf1, E);
    // 12) buf0 = swish(buf1 @ Wa[1,0] + ba[1,0])
    gemm_mma<128, 128, false, true, false><<<gblocks, 256, S_128_128>>>(
        buf1, W_res_a + 2 * DD * DD, b_res_a + 2 * DD, nullptr, nullptr, nullptr, buf0, E);
    // 13) out = buf1 + swish(buf0 @ Wa[1,1] + ba[1,1])
    gemm_mma<128, 128, false, true, true><<<gblocks, 256, S_128_128>>>(
        buf0, W_res_a + 3 * DD * DD, b_res_a + 3 * DD, buf1, nullptr, nullptr, out, E);
}

// round 5
// speedup vs baseline: 1.2962x; 1.2962x over previous
#include <cuda_runtime.h>
#include <cuda_bf16.h>
#include <cstdint>

#define EMAX 262144
#define DD   128
#define DAA  64

// ---------------------------------------------------------------------------
// Device scratch (no allocations allowed)
// ---------------------------------------------------------------------------
__device__ __align__(256) unsigned char g_pm [(size_t)EMAX * DD * 4];  // m_input planes
__device__ __align__(256) unsigned char g_p0 [(size_t)EMAX * DD * 4];
__device__ __align__(256) unsigned char g_p1 [(size_t)EMAX * DD * 4];
__device__ __align__(256) unsigned char g_pxd[(size_t)EMAX * DAA * 4]; // xdown planes
__device__ __align__(256) unsigned char g_pag[(size_t)EMAX * DAA * 4]; // agg planes
__device__ float g_agg[(size_t)EMAX * DAA];
__device__ float g_wrbf[6 * DD];
__device__ __align__(256) unsigned char g_wplanes[1 << 20];            // weight hi/lo planes

// ---------------------------------------------------------------------------
// PTX helpers (plain sm_103-legal)
// ---------------------------------------------------------------------------
__device__ __forceinline__ uint32_t smem_u32(const void* p) {
    uint32_t a;
    asm("{ .reg .u64 t; cvta.to.shared.u64 t, %1; cvt.u32.u64 %0, t; }"
        : "=r"(a) : "l"(p));
    return a;
}
__device__ __forceinline__ void cp_async16(uint32_t dst, const void* src) {
    asm volatile("cp.async.cg.shared.global [%0], [%1], 16;" :: "r"(dst), "l"(src));
}
__device__ __forceinline__ void cp_commit() {
    asm volatile("cp.async.commit_group;");
}
__device__ __forceinline__ void cp_wait1() {
    asm volatile("cp.async.wait_group 1;");
}
__device__ __forceinline__ void cp_wait0() {
    asm volatile("cp.async.wait_group 0;");
}
__device__ __forceinline__ void ldsm_x4(uint32_t& r0, uint32_t& r1,
                                        uint32_t& r2, uint32_t& r3, uint32_t addr) {
    asm volatile("ldmatrix.sync.aligned.m8n8.x4.shared.b16 {%0,%1,%2,%3}, [%4];"
                 : "=r"(r0), "=r"(r1), "=r"(r2), "=r"(r3) : "r"(addr));
}
__device__ __forceinline__ void mma_bf16(float* c, const uint32_t* a,
                                         uint32_t b0, uint32_t b1) {
    asm volatile(
        "mma.sync.aligned.m16n8k16.row.col.f32.bf16.bf16.f32 "
        "{%0,%1,%2,%3}, {%4,%5,%6,%7}, {%8,%9}, {%0,%1,%2,%3};"
        : "+f"(c[0]), "+f"(c[1]), "+f"(c[2]), "+f"(c[3])
        : "r"(a[0]), "r"(a[1]), "r"(a[2]), "r"(a[3]), "r"(b0), "r"(b1));
}
__device__ __forceinline__ uint32_t pk_bf2(__nv_bfloat16 a, __nv_bfloat16 b) {
    __nv_bfloat162 t(a, b);
    return *reinterpret_cast<uint32_t*>(&t);
}
__device__ __forceinline__ float swishf(float x) {
    return x * (1.0f / (1.0f + __expf(-x)));
}
__device__ __forceinline__ void red_add_v4(float* p, float4 v) {
    asm volatile("red.global.add.v4.f32 [%0], {%1, %2, %3, %4};"
                 :: "l"(p), "f"(v.x), "f"(v.y), "f"(v.z), "f"(v.w) : "memory");
}

// ---------------------------------------------------------------------------
// Utility kernels
// ---------------------------------------------------------------------------
__global__ void zero_kernel(float* __restrict__ p, int n4) {
    int i = blockIdx.x * blockDim.x + threadIdx.x;
    if (i < n4) *(float4*)&p[i * 4] = make_float4(0.f, 0.f, 0.f, 0.f);
}

__global__ void wrbf_kernel(const float* __restrict__ W1, const float* __restrict__ W2,
                            float* __restrict__ out) {
    int c = threadIdx.x;
    #pragma unroll
    for (int r = 0; r < 6; r++) {
        float s = 0.f;
        #pragma unroll
        for (int j = 0; j < 8; j++) s += W1[r * 8 + j] * W2[j * DD + c];
        out[r * DD + c] = s;
    }
}

// fp32 -> bf16 hi/lo plane pair
__global__ void conv_planes(const float* __restrict__ in,
                            __nv_bfloat16* __restrict__ hi,
                            __nv_bfloat16* __restrict__ lo, int n4) {
    int i = blockIdx.x * blockDim.x + threadIdx.x;
    if (i >= n4) return;
    float4 v = *(const float4*)&in[i * 4];
    __nv_bfloat16 h0 = __float2bfloat16(v.x), h1 = __float2bfloat16(v.y);
    __nv_bfloat16 h2 = __float2bfloat16(v.z), h3 = __float2bfloat16(v.w);
    __nv_bfloat16 l0 = __float2bfloat16(v.x - __bfloat162float(h0));
    __nv_bfloat16 l1 = __float2bfloat16(v.y - __bfloat162float(h1));
    __nv_bfloat16 l2 = __float2bfloat16(v.z - __bfloat162float(h2));
    __nv_bfloat16 l3 = __float2bfloat16(v.w - __bfloat162float(h3));
    uint2 hv; hv.x = pk_bf2(h0, h1); hv.y = pk_bf2(h2, h3);
    uint2 lv; lv.x = pk_bf2(l0, l1); lv.y = pk_bf2(l2, l3);
    *(uint2*)&hi[i * 4] = hv;
    *(uint2*)&lo[i * 4] = lv;
}

// Weight prep: W [NI,NO] row-major fp32 -> B^T planes in final smem layout:
// hi plane: NO rows, stride NI*2+16 bytes; lo plane follows (NO*STR bytes).
struct WJob { const float* w; int ni, no, off; };
struct WJobs { WJob j[11]; };

__global__ void wprep_kernel(WJobs jobs) {
    WJob jb = jobs.j[blockIdx.y];
    const int STRb = jb.ni * 2 + 16;
    const int tot = jb.ni * jb.no;
    const int plane = jb.no * STRb;
    for (int i = blockIdx.x * blockDim.x + threadIdx.x; i < tot;
         i += gridDim.x * blockDim.x) {
        int k = i / jb.no, n = i % jb.no;
        float v = jb.w[i];
        __nv_bfloat16 h = __float2bfloat16(v);
        __nv_bfloat16 l = __float2bfloat16(v - __bfloat162float(h));
        unsigned char* base = g_wplanes + jb.off + n * STRb + k * 2;
        *(__nv_bfloat16*)base = h;
        *(__nv_bfloat16*)(base + plane) = l;
    }
}

// ---------------------------------------------------------------------------
// Persistent HMMA GEMM on bf16 hi/lo planes.
//   A planes: compact gmem [nrows, NI] bf16 (hi, lo separate arrays)
//   B planes: pre-laid gmem bytes in exact smem layout (1:1 cp.async)
//   Y: planes (hi/lo) or fp32. 512 threads, BM=128, double-buffered A.
// ---------------------------------------------------------------------------
template <int NI, int NO, bool GATE, bool BIAS, bool RES, bool OUTF32>
__global__ __launch_bounds__(512, 1)
void gemm_pp(const __nv_bfloat16* __restrict__ a_hi, const __nv_bfloat16* __restrict__ a_lo,
             const unsigned char* __restrict__ bW,
             const float* __restrict__ bias,
             const __nv_bfloat16* __restrict__ res_hi, const __nv_bfloat16* __restrict__ res_lo,
             const float* __restrict__ rbf, const float* __restrict__ wrbf,
             __nv_bfloat16* __restrict__ y_hi, __nv_bfloat16* __restrict__ y_lo,
             float* __restrict__ yf, int nrows) {
    extern __shared__ char smem[];
    constexpr int STR  = NI * 2 + 16;                 // smem row bytes
    constexpr int APL  = 128 * STR;                   // one A plane
    constexpr int STGB = 128 * (NO + 4) * 4;          // fp32 C staging bytes
    constexpr int ASTG = (2 * APL > STGB) ? 2 * APL : STGB;  // stage slot
    constexpr int OFF_A = 3072;
    constexpr int OFF_B = OFF_A + 2 * ASTG;
    constexpr int WN = NO / 2;                        // warp n-extent (64/32)
    constexpr int NJ = WN / 8;
    constexpr int NG = WN / 16;

    const uint32_t sb = smem_u32(smem);
    const int tid = threadIdx.x;
    const int w = tid >> 5, lane = tid & 31;
    const int wm0 = (w & 7) * 16;
    const int wn0 = (w >> 3) * WN;
    const int lr = lane & 15, lk = (lane >> 4) * 8;

    const int ntiles = (nrows + 127) >> 7;
    const int t0 = blockIdx.x, G = gridDim.x;
    if (t0 >= ntiles) return;
    const int my_n = (ntiles - 1 - t0) / G + 1;

    auto load_tile = [&](int tile, int s) {
        const int row0 = tile << 7;
        constexpr int NCH = NI / 8;                   // 16B chunks per row per plane
        constexpr int TOT = 128 * NCH;
        #pragma unroll 4
        for (int i = tid; i < 2 * TOT; i += 512) {
            int plane = (i >= TOT);
            int rem = plane ? i - TOT : i;
            int r = rem / NCH, ch = rem % NCH;
            int rr = row0 + r; if (rr >= nrows) rr = nrows - 1;
            const __nv_bfloat16* src = (plane ? a_lo : a_hi) + (size_t)rr * NI + ch * 8;
            cp_async16(sb + OFF_A + s * ASTG + plane * APL + r * STR + ch * 16, src);
        }
    };

    // Prologue: gate weights, B (1:1 copy), first two A tiles
    if (GATE) {
        for (int i = tid; i < 6 * NO; i += 512) ((float*)smem)[i] = wrbf[i];
    }
    {
        constexpr int NB = NO * STR * 2 / 16;
        #pragma unroll 4
        for (int i = tid; i < NB; i += 512)
            cp_async16(sb + OFF_B + i * 16, bW + i * 16);
    }
    load_tile(t0, 0); cp_commit();
    load_tile(my_n > 1 ? t0 + G : t0, 1); cp_commit();

    for (int j = 0; j < my_n; j++) {
        const int tile = t0 + j * G, s = j & 1;
        const int row0 = tile << 7;
        cp_wait1();
        __syncthreads();

        // ---- MMA: 3 passes (Ah*Bh, Ah*Bl, Al*Bh) ----
        float acc[NJ][4];
        #pragma unroll
        for (int nj = 0; nj < NJ; nj++)
            #pragma unroll
            for (int q = 0; q < 4; q++) acc[nj][q] = 0.f;

        #pragma unroll
        for (int pass = 0; pass < 3; pass++) {
            const uint32_t abase = sb + OFF_A + s * ASTG + (pass == 2 ? APL : 0);
            const uint32_t bbase = sb + OFF_B + (pass == 1 ? NO * STR : 0);
            #pragma unroll
            for (int k0 = 0; k0 < NI; k0 += 16) {
                uint32_t a4[4];
                ldsm_x4(a4[0], a4[1], a4[2], a4[3],
                        abase + (uint32_t)((wm0 + lr) * STR + (k0 + lk) * 2));
                uint32_t b[NG][4];
                #pragma unroll
                for (int g = 0; g < NG; g++)
                    ldsm_x4(b[g][0], b[g][1], b[g][2], b[g][3],
                            bbase + (uint32_t)((wn0 + g * 16 + lr) * STR + (k0 + lk) * 2));
                #pragma unroll
                for (int nj = 0; nj < NJ; nj++)
                    mma_bf16(acc[nj], a4, b[nj >> 1][nj & 1], b[nj >> 1][(nj & 1) + 2]);
            }
        }
        __syncthreads();   // all warps done reading stage s

        // ---- Stage C (fp32) through consumed A buffer ----
        float* stg = (float*)(smem + OFF_A + s * ASTG);
        constexpr int SSTR = NO + 4;
        {
            const int sr = lane >> 2, sc = (lane & 3) * 2;
            #pragma unroll
            for (int nj = 0; nj < NJ; nj++) {
                int r = wm0 + sr, c = wn0 + nj * 8 + sc;
                *(float2*)&stg[r * SSTR + c]       = make_float2(acc[nj][0], acc[nj][1]);
                *(float2*)&stg[(r + 8) * SSTR + c] = make_float2(acc[nj][2], acc[nj][3]);
            }
        }
        __syncthreads();

        // ---- Coalesced epilogue ----
        constexpr int RV = NO / 4;
        for (int idx = tid; idx < 128 * RV; idx += 512) {
            int r = idx / RV, c = (idx % RV) * 4;
            int row = row0 + r;
            if (row >= nrows) continue;
            float4 v = *(float4*)&stg[r * SSTR + c];
            float o[4] = {v.x, v.y, v.z, v.w};
            if (BIAS) {
                float4 bv = *(const float4*)&bias[c];
                o[0] += bv.x; o[1] += bv.y; o[2] += bv.z; o[3] += bv.w;
            }
            #pragma unroll
            for (int q = 0; q < 4; q++) o[q] = swishf(o[q]);
            if (GATE) {
                float rv6[6];
                #pragma unroll
                for (int jj = 0; jj < 6; jj++) rv6[jj] = rbf[(size_t)row * 6 + jj];
                #pragma unroll
                for (int q = 0; q < 4; q++) {
                    float g = 0.f;
                    #pragma unroll
                    for (int jj = 0; jj < 6; jj++)
                        g += rv6[jj] * ((float*)smem)[jj * NO + c + q];
                    o[q] *= g;
                }
            }
            if (RES) {
                const __nv_bfloat162* rh = (const __nv_bfloat162*)(res_hi + (size_t)row * NO + c);
                const __nv_bfloat162* rl = (const __nv_bfloat162*)(res_lo + (size_t)row * NO + c);
                float2 h0 = __bfloat1622float2(rh[0]), h1 = __bfloat1622float2(rh[1]);
                float2 l0 = __bfloat1622float2(rl[0]), l1 = __bfloat1622float2(rl[1]);
                o[0] += h0.x + l0.x; o[1] += h0.y + l0.y;
                o[2] += h1.x + l1.x; o[3] += h1.y + l1.y;
            }
            if (OUTF32) {
                *(float4*)&yf[(size_t)row * NO + c] = make_float4(o[0], o[1], o[2], o[3]);
            } else {
                __nv_bfloat16 h[4], l[4];
                #pragma unroll
                for (int q = 0; q < 4; q++) {
                    h[q] = __float2bfloat16(o[q]);
                    l[q] = __float2bfloat16(o[q] - __bfloat162float(h[q]));
                }
                uint2 hv; hv.x = pk_bf2(h[0], h[1]); hv.y = pk_bf2(h[2], h[3]);
                uint2 lv; lv.x = pk_bf2(l[0], l[1]); lv.y = pk_bf2(l[2], l[3]);
                *(uint2*)&y_hi[(size_t)row * NO + c] = hv;
                *(uint2*)&y_lo[(size_t)row * NO + c] = lv;
            }
        }
        __syncthreads();   // stage s free for next prefetch

        int pf = t0 + (j + 2) * G;
        if (pf >= ntiles) pf = tile;   // dummy (keeps group accounting uniform)
        load_tile(pf, s); cp_commit();
    }
    cp_wait0();
}

// ---------------------------------------------------------------------------
// Triplet kernel: gather xdown planes -> sbf gate -> vector atomic scatter
// ---------------------------------------------------------------------------
#define TPB_TRIP 64
__global__ __launch_bounds__(256)
void triplet_kernel(const float* __restrict__ sbf, const int* __restrict__ expand,
                    const int* __restrict__ reduce, const float* __restrict__ Wsbf1,
                    const float* __restrict__ Wsbf2,
                    const __nv_bfloat16* __restrict__ xh,
                    const __nv_bfloat16* __restrict__ xl,
                    float* __restrict__ agg, int Ttot) {
    __shared__ float s_sbf[TPB_TRIP * 42];
    __shared__ float s_h[TPB_TRIP * 9];
    __shared__ float s_w1[42 * 8];
    __shared__ float s_w2[8 * 64];
    __shared__ int   s_ekj[TPB_TRIP];
    __shared__ int   s_eji[TPB_TRIP];

    const int tid  = threadIdx.x;
    const int base = blockIdx.x * TPB_TRIP;
    const int n_t  = min(TPB_TRIP, Ttot - base);

    for (int i = tid; i < 42 * 8; i += 256) s_w1[i] = Wsbf1[i];
    for (int i = tid; i < 8 * 64; i += 256) s_w2[i] = Wsbf2[i];
    for (int i = tid; i < n_t * 42; i += 256) s_sbf[i] = sbf[(size_t)base * 42 + i];
    if (tid < n_t) {
        s_ekj[tid] = expand[base + tid];
        s_eji[tid] = reduce[base + tid];
    }
    __syncthreads();

    for (int wi = tid; wi < n_t * 8; wi += 256) {
        int i = wi >> 3, j = wi & 7;
        float s = 0.f;
        #pragma unroll
        for (int k = 0; k < 42; k++) s += s_sbf[i * 42 + k] * s_w1[k * 8 + j];
        s_h[i * 9 + j] = s;
    }
    __syncthreads();

    const int trip = tid >> 2;
    const int c0   = (tid & 3) * 16;
    if (trip < n_t) {
        float h[8];
        #pragma unroll
        for (int j = 0; j < 8; j++) h[j] = s_h[trip * 9 + j];
        const int ekj = s_ekj[trip];
        const int eji = s_eji[trip];
        const __nv_bfloat162* hp = (const __nv_bfloat162*)(xh + (size_t)ekj * DAA + c0);
        const __nv_bfloat162* lp = (const __nv_bfloat162*)(xl + (size_t)ekj * DAA + c0);
        float* ap = agg + (size_t)eji * DAA + c0;
        #pragma unroll
        for (int q = 0; q < 4; q++) {
            float2 ha = __bfloat1622float2(hp[2 * q]);
            float2 hb = __bfloat1622float2(hp[2 * q + 1]);
            float2 la = __bfloat1622float2(lp[2 * q]);
            float2 lb = __bfloat1622float2(lp[2 * q + 1]);
            float4 x = make_float4(ha.x + la.x, ha.y + la.y, hb.x + lb.x, hb.y + lb.y);
            int cb = c0 + q * 4;
            float g0 = 0.f, g1 = 0.f, g2 = 0.f, g3 = 0.f;
            #pragma unroll
            for (int j = 0; j < 8; j++) {
                float4 wv = *(const float4*)&s_w2[j * 64 + cb];
                float hj = h[j];
                g0 += hj * wv.x; g1 += hj * wv.y; g2 += hj * wv.z; g3 += hj * wv.w;
            }
            red_add_v4(ap + q * 4, make_float4(x.x * g0, x.y * g1, x.z * g2, x.w * g3));
        }
    }
}

// ---------------------------------------------------------------------------
// Host launcher
// ---------------------------------------------------------------------------
static inline int smem_pp(int NI, int NO) {
    int STR = NI * 2 + 16;
    int APL = 128 * STR;
    int STGB = 128 * (NO + 4) * 4;
    int ASTG = (2 * APL > STGB) ? 2 * APL : STGB;
    return 3072 + 2 * ASTG + NO * STR * 2;
}

extern "C" void kernel_launch(void* const* d_in, const int* in_sizes, int n_in,
                              void* d_out, int out_size) {
    const float* m_input = (const float*)d_in[0];
    const float* rbf     = (const float*)d_in[1];
    const float* sbf     = (const float*)d_in[2];
    const int*   expand  = (const int*)d_in[3];
    const int*   reduce  = (const int*)d_in[4];
    const float* W_kj    = (const float*)d_in[5];
    const float* b_kj    = (const float*)d_in[6];
    const float* W_rbf1  = (const float*)d_in[7];
    const float* W_rbf2  = (const float*)d_in[8];
    const float* W_sbf1  = (const float*)d_in[9];
    const float* W_sbf2  = (const float*)d_in[10];
    const float* W_down  = (const float*)d_in[11];
    const float* W_up    = (const float*)d_in[12];
    const float* W_ji    = (const float*)d_in[13];
    const float* b_ji    = (const float*)d_in[14];
    const float* W_res_b = (const float*)d_in[15];
    const float* b_res_b = (const float*)d_in[16];
    const float* W_final = (const float*)d_in[17];
    const float* b_final = (const float*)d_in[18];
    const float* W_res_a = (const float*)d_in[19];
    const float* b_res_a = (const float*)d_in[20];
    float* out = (float*)d_out;

    const int E = in_sizes[0] / DD;
    const int T = in_sizes[3];

    unsigned char *pm, *p0, *p1, *pxd, *pag, *wp;
    float *agg, *wrbf;
    cudaGetSymbolAddress((void**)&pm,  g_pm);
    cudaGetSymbolAddress((void**)&p0,  g_p0);
    cudaGetSymbolAddress((void**)&p1,  g_p1);
    cudaGetSymbolAddress((void**)&pxd, g_pxd);
    cudaGetSymbolAddress((void**)&pag, g_pag);
    cudaGetSymbolAddress((void**)&agg, g_agg);
    cudaGetSymbolAddress((void**)&wrbf, g_wrbf);
    cudaGetSymbolAddress((void**)&wp,  g_wplanes);

    typedef __nv_bfloat16 bf;
    const size_t plD  = (size_t)E * DD;   // elems per 128-col plane
    const size_t plA  = (size_t)E * DAA;  // elems per 64-col plane
    bf *pm_h  = (bf*)pm,  *pm_l  = (bf*)pm  + plD;
    bf *p0_h  = (bf*)p0,  *p0_l  = (bf*)p0  + plD;
    bf *p1_h  = (bf*)p1,  *p1_l  = (bf*)p1  + plD;
    bf *pxd_h = (bf*)pxd, *pxd_l = (bf*)pxd + plA;
    bf *pag_h = (bf*)pag, *pag_l = (bf*)pag + plA;

    int smcnt = 148, dev = 0;
    cudaGetDevice(&dev);
    cudaDeviceGetAttribute(&smcnt, cudaDevAttrMultiProcessorCount, dev);
    const int ntiles = (E + 127) / 128;
    const int grid = (ntiles < smcnt) ? ntiles : smcnt;

    const int S11 = smem_pp(128, 128);
    const int S16 = smem_pp(128, 64);
    const int S61 = smem_pp(64, 128);
    cudaFuncSetAttribute(gemm_pp<128,128,true, true, false,false>, cudaFuncAttributeMaxDynamicSharedMemorySize, S11);
    cudaFuncSetAttribute(gemm_pp<128,64, false,false,false,false>, cudaFuncAttributeMaxDynamicSharedMemorySize, S16);
    cudaFuncSetAttribute(gemm_pp<64, 128,false,false,false,false>, cudaFuncAttributeMaxDynamicSharedMemorySize, S61);
    cudaFuncSetAttribute(gemm_pp<128,128,false,true, true, false>, cudaFuncAttributeMaxDynamicSharedMemorySize, S11);
    cudaFuncSetAttribute(gemm_pp<128,128,false,true, false,false>, cudaFuncAttributeMaxDynamicSharedMemorySize, S11);
    cudaFuncSetAttribute(gemm_pp<128,128,false,true, true, true >, cudaFuncAttributeMaxDynamicSharedMemorySize, S11);

    // Weight plane offsets
    const int PP = 69632;   // 128x128 pair bytes
    const int OFF_DOWN = 9 * PP;            // 626688
    const int OFF_UP   = OFF_DOWN + 34816;  // 661504

    // 0) zero agg
    zero_kernel<<<(E * DAA / 4 + 255) / 256, 256>>>(agg, E * DAA / 4);
    // 1) fused rbf weights
    wrbf_kernel<<<1, 128>>>(W_rbf1, W_rbf2, wrbf);
    // 2) weight planes
    {
        WJobs jobs;
        jobs.j[0]  = {W_kj,               128, 128, 0 * PP};
        jobs.j[1]  = {W_ji,               128, 128, 1 * PP};
        jobs.j[2]  = {W_res_b,            128, 128, 2 * PP};
        jobs.j[3]  = {W_res_b + 16384,    128, 128, 3 * PP};
        jobs.j[4]  = {W_final,            128, 128, 4 * PP};
        jobs.j[5]  = {W_res_a,            128, 128, 5 * PP};
        jobs.j[6]  = {W_res_a + 16384,    128, 128, 6 * PP};
        jobs.j[7]  = {W_res_a + 32768,    128, 128, 7 * PP};
        jobs.j[8]  = {W_res_a + 49152,    128, 128, 8 * PP};
        jobs.j[9]  = {W_down,             128, 64,  OFF_DOWN};
        jobs.j[10] = {W_up,               64,  128, OFF_UP};
        dim3 g(64, 11);
        wprep_kernel<<<g, 256>>>(jobs);
    }
    // 3) m_input -> planes
    conv_planes<<<(E * DD / 4 + 255) / 256, 256>>>(m_input, pm_h, pm_l, E * DD / 4);

    // 4) p0 = swish(m@W_kj+b) * rbf_gate
    gemm_pp<128,128,true,true,false,false><<<grid, 512, S11>>>(
        pm_h, pm_l, wp + 0 * PP, b_kj, nullptr, nullptr, rbf, wrbf,
        p0_h, p0_l, nullptr, E);
    // 5) pxd = swish(p0 @ W_down)
    gemm_pp<128,64,false,false,false,false><<<grid, 512, S16>>>(
        p0_h, p0_l, wp + OFF_DOWN, nullptr, nullptr, nullptr, nullptr, nullptr,
        pxd_h, pxd_l, nullptr, E);
    // 6) triplet gather/gate/scatter
    triplet_kernel<<<(T + TPB_TRIP - 1) / TPB_TRIP, 256>>>(
        sbf, expand, reduce, W_sbf1, W_sbf2, pxd_h, pxd_l, agg, T);
    // 7) agg -> planes
    conv_planes<<<(E * DAA / 4 + 255) / 256, 256>>>(agg, pag_h, pag_l, E * DAA / 4);
    // 8) p1 = swish(agg @ W_up)
    gemm_pp<64,128,false,false,false,false><<<grid, 512, S61>>>(
        pag_h, pag_l, wp + OFF_UP, nullptr, nullptr, nullptr, nullptr, nullptr,
        p1_h, p1_l, nullptr, E);
    // 9) p0 = swish(m@W_ji+b) + p1
    gemm_pp<128,128,false,true,true,false><<<grid, 512, S11>>>(
        pm_h, pm_l, wp + 1 * PP, b_ji, p1_h, p1_l, nullptr, nullptr,
        p0_h, p0_l, nullptr, E);
    // 10) p1 = swish(p0@Wb0+b)
    gemm_pp<128,128,false,true,false,false><<<grid, 512, S11>>>(
        p0_h, p0_l, wp + 2 * PP, b_res_b, nullptr, nullptr, nullptr, nullptr,
        p1_h, p1_l, nullptr, E);
    // 11) p1 = p0 + swish(p1@Wb1+b)   (in-place A)
    gemm_pp<128,128,false,true,true,false><<<grid, 512, S11>>>(
        p1_h, p1_l, wp + 3 * PP, b_res_b + DD, p0_h, p0_l, nullptr, nullptr,
        p1_h, p1_l, nullptr, E);
    // 12) p0 = swish(p1@W_final+b) + m
    gemm_pp<128,128,false,true,true,false><<<grid, 512, S11>>>(
        p1_h, p1_l, wp + 4 * PP, b_final, pm_h, pm_l, nullptr, nullptr,
        p0_h, p0_l, nullptr, E);
    // 13) p1 = swish(p0@Wa00+b)
    gemm_pp<128,128,false,true,false,false><<<grid, 512, S11>>>(
        p0_h, p0_l, wp + 5 * PP, b_res_a, nullptr, nullptr, nullptr, nullptr,
        p1_h, p1_l, nullptr, E);
    // 14) p1 = p0 + swish(p1@Wa01+b)
    gemm_pp<128,128,false,true,true,false><<<grid, 512, S11>>>(
        p1_h, p1_l, wp + 6 * PP, b_res_a + DD, p0_h, p0_l, nullptr, nullptr,
        p1_h, p1_l, nullptr, E);
    // 15) p0 = swish(p1@Wa10+b)
    gemm_pp<128,128,false,true,false,false><<<grid, 512, S11>>>(
        p1_h, p1_l, wp + 7 * PP, b_res_a + 2 * DD, nullptr, nullptr, nullptr, nullptr,
        p0_h, p0_l, nullptr, E);
    // 16) out = p1 + swish(p0@Wa11+b)   (fp32 output)
    gemm_pp<128,128,false,true,true,true><<<grid, 512, S11>>>(
        p0_h, p0_l, wp + 8 * PP, b_res_a + 3 * DD, p1_h, p1_l, nullptr, nullptr,
        nullptr, nullptr, out, E);
}

// round 6
// speedup vs baseline: 1.9890x; 1.5344x over previous
#include <cuda_runtime.h>
#include <cuda_bf16.h>
#include <cstdint>

#define EMAX 262144
#define DD   128
#define DAA  64

// ---------------------------------------------------------------------------
// Device scratch (no allocations allowed)
// ---------------------------------------------------------------------------
__device__ __align__(256) unsigned char g_pm [(size_t)EMAX * DD * 4];  // m_input planes
__device__ __align__(256) unsigned char g_p0 [(size_t)EMAX * DD * 4];
__device__ __align__(256) unsigned char g_p1 [(size_t)EMAX * DD * 4];
__device__ __align__(256) unsigned char g_pxd[(size_t)EMAX * DAA * 4]; // xdown planes
__device__ __align__(256) unsigned char g_pag[(size_t)EMAX * DAA * 4]; // agg planes
__device__ float g_agg[(size_t)EMAX * DAA];
__device__ float g_wrbf[6 * DD];
__device__ __align__(256) unsigned char g_wplanes[1 << 20];            // weight hi/lo planes

// ---------------------------------------------------------------------------
// PTX helpers (plain sm_103-legal)
// ---------------------------------------------------------------------------
__device__ __forceinline__ uint32_t smem_u32(const void* p) {
    uint32_t a;
    asm("{ .reg .u64 t; cvta.to.shared.u64 t, %1; cvt.u32.u64 %0, t; }"
        : "=r"(a) : "l"(p));
    return a;
}
__device__ __forceinline__ void cp_async16(uint32_t dst, const void* src) {
    asm volatile("cp.async.cg.shared.global [%0], [%1], 16;" :: "r"(dst), "l"(src));
}
__device__ __forceinline__ void cp_commit() {
    asm volatile("cp.async.commit_group;");
}
__device__ __forceinline__ void cp_wait1() {
    asm volatile("cp.async.wait_group 1;");
}
__device__ __forceinline__ void cp_wait0() {
    asm volatile("cp.async.wait_group 0;");
}
__device__ __forceinline__ void ldsm_x4(uint32_t& r0, uint32_t& r1,
                                        uint32_t& r2, uint32_t& r3, uint32_t addr) {
    asm volatile("ldmatrix.sync.aligned.m8n8.x4.shared.b16 {%0,%1,%2,%3}, [%4];"
                 : "=r"(r0), "=r"(r1), "=r"(r2), "=r"(r3) : "r"(addr));
}
__device__ __forceinline__ void mma_bf16(float* c, const uint32_t* a,
                                         uint32_t b0, uint32_t b1) {
    asm volatile(
        "mma.sync.aligned.m16n8k16.row.col.f32.bf16.bf16.f32 "
        "{%0,%1,%2,%3}, {%4,%5,%6,%7}, {%8,%9}, {%0,%1,%2,%3};"
        : "+f"(c[0]), "+f"(c[1]), "+f"(c[2]), "+f"(c[3])
        : "r"(a[0]), "r"(a[1]), "r"(a[2]), "r"(a[3]), "r"(b0), "r"(b1));
}
__device__ __forceinline__ uint32_t pk_bf2(__nv_bfloat16 a, __nv_bfloat16 b) {
    __nv_bfloat162 t(a, b);
    return *reinterpret_cast<uint32_t*>(&t);
}
__device__ __forceinline__ float swishf(float x) {
    return x * (1.0f / (1.0f + __expf(-x)));
}
__device__ __forceinline__ void red_add_v4(float* p, float4 v) {
    asm volatile("red.global.add.v4.f32 [%0], {%1, %2, %3, %4};"
                 :: "l"(p), "f"(v.x), "f"(v.y), "f"(v.z), "f"(v.w) : "memory");
}

// ---------------------------------------------------------------------------
// Utility kernels
// ---------------------------------------------------------------------------
__global__ void zero_kernel(float* __restrict__ p, int n4) {
    int i = blockIdx.x * blockDim.x + threadIdx.x;
    if (i < n4) *(float4*)&p[i * 4] = make_float4(0.f, 0.f, 0.f, 0.f);
}

__global__ void wrbf_kernel(const float* __restrict__ W1, const float* __restrict__ W2,
                            float* __restrict__ out) {
    int c = threadIdx.x;
    #pragma unroll
    for (int r = 0; r < 6; r++) {
        float s = 0.f;
        #pragma unroll
        for (int j = 0; j < 8; j++) s += W1[r * 8 + j] * W2[j * DD + c];
        out[r * DD + c] = s;
    }
}

// fp32 -> bf16 hi/lo plane pair
__global__ void conv_planes(const float* __restrict__ in,
                            __nv_bfloat16* __restrict__ hi,
                            __nv_bfloat16* __restrict__ lo, int n4) {
    int i = blockIdx.x * blockDim.x + threadIdx.x;
    if (i >= n4) return;
    float4 v = *(const float4*)&in[i * 4];
    __nv_bfloat16 h0 = __float2bfloat16(v.x), h1 = __float2bfloat16(v.y);
    __nv_bfloat16 h2 = __float2bfloat16(v.z), h3 = __float2bfloat16(v.w);
    __nv_bfloat16 l0 = __float2bfloat16(v.x - __bfloat162float(h0));
    __nv_bfloat16 l1 = __float2bfloat16(v.y - __bfloat162float(h1));
    __nv_bfloat16 l2 = __float2bfloat16(v.z - __bfloat162float(h2));
    __nv_bfloat16 l3 = __float2bfloat16(v.w - __bfloat162float(h3));
    uint2 hv; hv.x = pk_bf2(h0, h1); hv.y = pk_bf2(h2, h3);
    uint2 lv; lv.x = pk_bf2(l0, l1); lv.y = pk_bf2(l2, l3);
    *(uint2*)&hi[i * 4] = hv;
    *(uint2*)&lo[i * 4] = lv;
}

// Weight prep: W [NI,NO] row-major fp32 -> B^T planes in final smem layout
struct WJob { const float* w; int ni, no, off; };
struct WJobs { WJob j[11]; };

__global__ void wprep_kernel(WJobs jobs) {
    WJob jb = jobs.j[blockIdx.y];
    const int STRb = jb.ni * 2 + 16;
    const int tot = jb.ni * jb.no;
    const int plane = jb.no * STRb;
    for (int i = blockIdx.x * blockDim.x + threadIdx.x; i < tot;
         i += gridDim.x * blockDim.x) {
        int k = i / jb.no, n = i % jb.no;
        float v = jb.w[i];
        __nv_bfloat16 h = __float2bfloat16(v);
        __nv_bfloat16 l = __float2bfloat16(v - __bfloat162float(h));
        unsigned char* base = g_wplanes + jb.off + n * STRb + k * 2;
        *(__nv_bfloat16*)base = h;
        *(__nv_bfloat16*)(base + plane) = l;
    }
}

// ---------------------------------------------------------------------------
// Persistent HMMA GEMM on bf16 hi/lo planes — 1024 threads (32 warps) to
// hide ldsm->mma latency (R4/R5 showed tensor pipe ~12% busy at 8-16 warps).
// Warp tile: 16 x (NO/4). BM=128, double-buffered A stages via cp.async.
// ---------------------------------------------------------------------------
template <int NI, int NO, bool GATE, bool BIAS, bool RES, bool OUTF32>
__global__ __launch_bounds__(1024, 1)
void gemm_pp(const __nv_bfloat16* __restrict__ a_hi, const __nv_bfloat16* __restrict__ a_lo,
             const unsigned char* __restrict__ bW,
             const float* __restrict__ bias,
             const __nv_bfloat16* __restrict__ res_hi, const __nv_bfloat16* __restrict__ res_lo,
             const float* __restrict__ rbf, const float* __restrict__ wrbf,
             __nv_bfloat16* __restrict__ y_hi, __nv_bfloat16* __restrict__ y_lo,
             float* __restrict__ yf, int nrows) {
    extern __shared__ char smem[];
    constexpr int STR  = NI * 2 + 16;                 // smem row bytes
    constexpr int APL  = 128 * STR;                   // one A plane
    constexpr int STGB = 128 * (NO + 4) * 4;          // fp32 C staging bytes
    constexpr int ASTG = (2 * APL > STGB) ? 2 * APL : STGB;  // stage slot
    constexpr int OFF_A = 3072;
    constexpr int OFF_B = OFF_A + 2 * ASTG;
    constexpr int WN = NO / 4;                        // warp n-extent (32 or 16)
    constexpr int NJ = WN / 8;                        // 4 or 2
    constexpr int NG = WN / 16;                       // 2 or 1
    constexpr int NT = 1024;

    const uint32_t sb = smem_u32(smem);
    const int tid = threadIdx.x;
    const int w = tid >> 5, lane = tid & 31;
    const int wm0 = (w & 7) * 16;                     // 8 m-slices
    const int wn0 = (w >> 3) * WN;                    // 4 n-slices
    const int lr = lane & 15, lk = (lane >> 4) * 8;

    const int ntiles = (nrows + 127) >> 7;
    const int t0 = blockIdx.x, G = gridDim.x;
    if (t0 >= ntiles) return;
    const int my_n = (ntiles - 1 - t0) / G + 1;

    auto load_tile = [&](int tile, int s) {
        const int row0 = tile << 7;
        constexpr int NCH = NI / 8;                   // 16B chunks per row per plane
        constexpr int TOT = 128 * NCH;
        #pragma unroll 4
        for (int i = tid; i < 2 * TOT; i += NT) {
            int plane = (i >= TOT);
            int rem = plane ? i - TOT : i;
            int r = rem / NCH, ch = rem % NCH;
            int rr = row0 + r; if (rr >= nrows) rr = nrows - 1;
            const __nv_bfloat16* src = (plane ? a_lo : a_hi) + (size_t)rr * NI + ch * 8;
            cp_async16(sb + OFF_A + s * ASTG + plane * APL + r * STR + ch * 16, src);
        }
    };

    // Prologue: gate weights, B (1:1 byte copy), first two A tiles
    if (GATE) {
        for (int i = tid; i < 6 * NO; i += NT) ((float*)smem)[i] = wrbf[i];
    }
    {
        constexpr int NB = NO * STR * 2 / 16;
        #pragma unroll 4
        for (int i = tid; i < NB; i += NT)
            cp_async16(sb + OFF_B + i * 16, bW + i * 16);
    }
    load_tile(t0, 0); cp_commit();
    load_tile(my_n > 1 ? t0 + G : t0, 1); cp_commit();

    for (int j = 0; j < my_n; j++) {
        const int tile = t0 + j * G, s = j & 1;
        const int row0 = tile << 7;
        cp_wait1();
        __syncthreads();

        // ---- MMA: 3 passes (Ah*Bh, Ah*Bl, Al*Bh) ----
        float acc[NJ][4];
        #pragma unroll
        for (int nj = 0; nj < NJ; nj++)
            #pragma unroll
            for (int q = 0; q < 4; q++) acc[nj][q] = 0.f;

        #pragma unroll
        for (int pass = 0; pass < 3; pass++) {
            const uint32_t abase = sb + OFF_A + s * ASTG + (pass == 2 ? APL : 0);
            const uint32_t bbase = sb + OFF_B + (pass == 1 ? NO * STR : 0);
            #pragma unroll
            for (int k0 = 0; k0 < NI; k0 += 16) {
                uint32_t a4[4];
                ldsm_x4(a4[0], a4[1], a4[2], a4[3],
                        abase + (uint32_t)((wm0 + lr) * STR + (k0 + lk) * 2));
                uint32_t b[NG][4];
                #pragma unroll
                for (int g = 0; g < NG; g++)
                    ldsm_x4(b[g][0], b[g][1], b[g][2], b[g][3],
                            bbase + (uint32_t)((wn0 + g * 16 + lr) * STR + (k0 + lk) * 2));
                #pragma unroll
                for (int nj = 0; nj < NJ; nj++)
                    mma_bf16(acc[nj], a4, b[nj >> 1][nj & 1], b[nj >> 1][(nj & 1) + 2]);
            }
        }
        __syncthreads();   // all warps done reading stage s

        // ---- Stage C (fp32) through consumed A buffer ----
        float* stg = (float*)(smem + OFF_A + s * ASTG);
        constexpr int SSTR = NO + 4;
        {
            const int sr = lane >> 2, sc = (lane & 3) * 2;
            #pragma unroll
            for (int nj = 0; nj < NJ; nj++) {
                int r = wm0 + sr, c = wn0 + nj * 8 + sc;
                *(float2*)&stg[r * SSTR + c]       = make_float2(acc[nj][0], acc[nj][1]);
                *(float2*)&stg[(r + 8) * SSTR + c] = make_float2(acc[nj][2], acc[nj][3]);
            }
        }
        __syncthreads();

        // ---- Coalesced epilogue ----
        constexpr int RV = NO / 4;
        for (int idx = tid; idx < 128 * RV; idx += NT) {
            int r = idx / RV, c = (idx % RV) * 4;
            int row = row0 + r;
            if (row >= nrows) continue;
            float4 v = *(float4*)&stg[r * SSTR + c];
            float o[4] = {v.x, v.y, v.z, v.w};
            if (BIAS) {
                float4 bv = *(const float4*)&bias[c];
                o[0] += bv.x; o[1] += bv.y; o[2] += bv.z; o[3] += bv.w;
            }
            #pragma unroll
            for (int q = 0; q < 4; q++) o[q] = swishf(o[q]);
            if (GATE) {
                float rv6[6];
                #pragma unroll
                for (int jj = 0; jj < 6; jj++) rv6[jj] = rbf[(size_t)row * 6 + jj];
                #pragma unroll
                for (int q = 0; q < 4; q++) {
                    float g = 0.f;
                    #pragma unroll
                    for (int jj = 0; jj < 6; jj++)
                        g += rv6[jj] * ((float*)smem)[jj * NO + c + q];
                    o[q] *= g;
                }
            }
            if (RES) {
                const __nv_bfloat162* rh = (const __nv_bfloat162*)(res_hi + (size_t)row * NO + c);
                const __nv_bfloat162* rl = (const __nv_bfloat162*)(res_lo + (size_t)row * NO + c);
                float2 h0 = __bfloat1622float2(rh[0]), h1 = __bfloat1622float2(rh[1]);
                float2 l0 = __bfloat1622float2(rl[0]), l1 = __bfloat1622float2(rl[1]);
                o[0] += h0.x + l0.x; o[1] += h0.y + l0.y;
                o[2] += h1.x + l1.x; o[3] += h1.y + l1.y;
            }
            if (OUTF32) {
                *(float4*)&yf[(size_t)row * NO + c] = make_float4(o[0], o[1], o[2], o[3]);
            } else {
                __nv_bfloat16 h[4], l[4];
                #pragma unroll
                for (int q = 0; q < 4; q++) {
                    h[q] = __float2bfloat16(o[q]);
                    l[q] = __float2bfloat16(o[q] - __bfloat162float(h[q]));
                }
                uint2 hv; hv.x = pk_bf2(h[0], h[1]); hv.y = pk_bf2(h[2], h[3]);
                uint2 lv; lv.x = pk_bf2(l[0], l[1]); lv.y = pk_bf2(l[2], l[3]);
                *(uint2*)&y_hi[(size_t)row * NO + c] = hv;
                *(uint2*)&y_lo[(size_t)row * NO + c] = lv;
            }
        }
        __syncthreads();   // stage s free for next prefetch

        int pf = t0 + (j + 2) * G;
        if (pf >= ntiles) pf = tile;   // dummy (keeps group accounting uniform)
        load_tile(pf, s); cp_commit();
    }
    cp_wait0();
}

// ---------------------------------------------------------------------------
// Triplet kernel: gather xdown planes -> sbf gate -> vector atomic scatter
// ---------------------------------------------------------------------------
#define TPB_TRIP 64
__global__ __launch_bounds__(256)
void triplet_kernel(const float* __restrict__ sbf, const int* __restrict__ expand,
                    const int* __restrict__ reduce, const float* __restrict__ Wsbf1,
                    const float* __restrict__ Wsbf2,
                    const __nv_bfloat16* __restrict__ xh,
                    const __nv_bfloat16* __restrict__ xl,
                    float* __restrict__ agg, int Ttot) {
    __shared__ float s_sbf[TPB_TRIP * 42];
    __shared__ float s_h[TPB_TRIP * 9];
    __shared__ float s_w1[42 * 8];
    __shared__ float s_w2[8 * 64];
    __shared__ int   s_ekj[TPB_TRIP];
    __shared__ int   s_eji[TPB_TRIP];

    const int tid  = threadIdx.x;
    const int base = blockIdx.x * TPB_TRIP;
    const int n_t  = min(TPB_TRIP, Ttot - base);

    for (int i = tid; i < 42 * 8; i += 256) s_w1[i] = Wsbf1[i];
    for (int i = tid; i < 8 * 64; i += 256) s_w2[i] = Wsbf2[i];
    for (int i = tid; i < n_t * 42; i += 256) s_sbf[i] = sbf[(size_t)base * 42 + i];
    if (tid < n_t) {
        s_ekj[tid] = expand[base + tid];
        s_eji[tid] = reduce[base + tid];
    }
    __syncthreads();

    for (int wi = tid; wi < n_t * 8; wi += 256) {
        int i = wi >> 3, j = wi & 7;
        float s = 0.f;
        #pragma unroll
        for (int k = 0; k < 42; k++) s += s_sbf[i * 42 + k] * s_w1[k * 8 + j];
        s_h[i * 9 + j] = s;
    }
    __syncthreads();

    const int trip = tid >> 2;
    const int c0   = (tid & 3) * 16;
    if (trip < n_t) {
        float h[8];
        #pragma unroll
        for (int j = 0; j < 8; j++) h[j] = s_h[trip * 9 + j];
        const int ekj = s_ekj[trip];
        const int eji = s_eji[trip];
        const __nv_bfloat162* hp = (const __nv_bfloat162*)(xh + (size_t)ekj * DAA + c0);
        const __nv_bfloat162* lp = (const __nv_bfloat162*)(xl + (size_t)ekj * DAA + c0);
        float* ap = agg + (size_t)eji * DAA + c0;
        #pragma unroll
        for (int q = 0; q < 4; q++) {
            float2 ha = __bfloat1622float2(hp[2 * q]);
            float2 hb = __bfloat1622float2(hp[2 * q + 1]);
            float2 la = __bfloat1622float2(lp[2 * q]);
            float2 lb = __bfloat1622float2(lp[2 * q + 1]);
            float4 x = make_float4(ha.x + la.x, ha.y + la.y, hb.x + lb.x, hb.y + lb.y);
            int cb = c0 + q * 4;
            float g0 = 0.f, g1 = 0.f, g2 = 0.f, g3 = 0.f;
            #pragma unroll
            for (int j = 0; j < 8; j++) {
                float4 wv = *(const float4*)&s_w2[j * 64 + cb];
                float hj = h[j];
                g0 += hj * wv.x; g1 += hj * wv.y; g2 += hj * wv.z; g3 += hj * wv.w;
            }
            red_add_v4(ap + q * 4, make_float4(x.x * g0, x.y * g1, x.z * g2, x.w * g3));
        }
    }
}

// ---------------------------------------------------------------------------
// Host launcher
// ---------------------------------------------------------------------------
static inline int smem_pp(int NI, int NO) {
    int STR = NI * 2 + 16;
    int APL = 128 * STR;
    int STGB = 128 * (NO + 4) * 4;
    int ASTG = (2 * APL > STGB) ? 2 * APL : STGB;
    return 3072 + 2 * ASTG + NO * STR * 2;
}

extern "C" void kernel_launch(void* const* d_in, const int* in_sizes, int n_in,
                              void* d_out, int out_size) {
    const float* m_input = (const float*)d_in[0];
    const float* rbf     = (const float*)d_in[1];
    const float* sbf     = (const float*)d_in[2];
    const int*   expand  = (const int*)d_in[3];
    const int*   reduce  = (const int*)d_in[4];
    const float* W_kj    = (const float*)d_in[5];
    const float* b_kj    = (const float*)d_in[6];
    const float* W_rbf1  = (const float*)d_in[7];
    const float* W_rbf2  = (const float*)d_in[8];
    const float* W_sbf1  = (const float*)d_in[9];
    const float* W_sbf2  = (const float*)d_in[10];
    const float* W_down  = (const float*)d_in[11];
    const float* W_up    = (const float*)d_in[12];
    const float* W_ji    = (const float*)d_in[13];
    const float* b_ji    = (const float*)d_in[14];
    const float* W_res_b = (const float*)d_in[15];
    const float* b_res_b = (const float*)d_in[16];
    const float* W_final = (const float*)d_in[17];
    const float* b_final = (const float*)d_in[18];
    const float* W_res_a = (const float*)d_in[19];
    const float* b_res_a = (const float*)d_in[20];
    float* out = (float*)d_out;

    const int E = in_sizes[0] / DD;
    const int T = in_sizes[3];

    unsigned char *pm, *p0, *p1, *pxd, *pag, *wp;
    float *agg, *wrbf;
    cudaGetSymbolAddress((void**)&pm,  g_pm);
    cudaGetSymbolAddress((void**)&p0,  g_p0);
    cudaGetSymbolAddress((void**)&p1,  g_p1);
    cudaGetSymbolAddress((void**)&pxd, g_pxd);
    cudaGetSymbolAddress((void**)&pag, g_pag);
    cudaGetSymbolAddress((void**)&agg, g_agg);
    cudaGetSymbolAddress((void**)&wrbf, g_wrbf);
    cudaGetSymbolAddress((void**)&wp,  g_wplanes);

    typedef __nv_bfloat16 bf;
    const size_t plD  = (size_t)E * DD;
    const size_t plA  = (size_t)E * DAA;
    bf *pm_h  = (bf*)pm,  *pm_l  = (bf*)pm  + plD;
    bf *p0_h  = (bf*)p0,  *p0_l  = (bf*)p0  + plD;
    bf *p1_h  = (bf*)p1,  *p1_l  = (bf*)p1  + plD;
    bf *pxd_h = (bf*)pxd, *pxd_l = (bf*)pxd + plA;
    bf *pag_h = (bf*)pag, *pag_l = (bf*)pag + plA;

    int smcnt = 148, dev = 0;
    cudaGetDevice(&dev);
    cudaDeviceGetAttribute(&smcnt, cudaDevAttrMultiProcessorCount, dev);
    const int ntiles = (E + 127) / 128;
    const int grid = (ntiles < smcnt) ? ntiles : smcnt;

    const int S11 = smem_pp(128, 128);
    const int S16 = smem_pp(128, 64);
    const int S61 = smem_pp(64, 128);
    cudaFuncSetAttribute(gemm_pp<128,128,true, true, false,false>, cudaFuncAttributeMaxDynamicSharedMemorySize, S11);
    cudaFuncSetAttribute(gemm_pp<128,64, false,false,false,false>, cudaFuncAttributeMaxDynamicSharedMemorySize, S16);
    cudaFuncSetAttribute(gemm_pp<64, 128,false,false,false,false>, cudaFuncAttributeMaxDynamicSharedMemorySize, S61);
    cudaFuncSetAttribute(gemm_pp<128,128,false,true, true, false>, cudaFuncAttributeMaxDynamicSharedMemorySize, S11);
    cudaFuncSetAttribute(gemm_pp<128,128,false,true, false,false>, cudaFuncAttributeMaxDynamicSharedMemorySize, S11);
    cudaFuncSetAttribute(gemm_pp<128,128,false,true, true, true >, cudaFuncAttributeMaxDynamicSharedMemorySize, S11);

    const int PP = 69632;                   // 128x128 pair bytes
    const int OFF_DOWN = 9 * PP;
    const int OFF_UP   = OFF_DOWN + 34816;

    zero_kernel<<<(E * DAA / 4 + 255) / 256, 256>>>(agg, E * DAA / 4);
    wrbf_kernel<<<1, 128>>>(W_rbf1, W_rbf2, wrbf);
    {
        WJobs jobs;
        jobs.j[0]  = {W_kj,               128, 128, 0 * PP};
        jobs.j[1]  = {W_ji,               128, 128, 1 * PP};
        jobs.j[2]  = {W_res_b,            128, 128, 2 * PP};
        jobs.j[3]  = {W_res_b + 16384,    128, 128, 3 * PP};
        jobs.j[4]  = {W_final,            128, 128, 4 * PP};
        jobs.j[5]  = {W_res_a,            128, 128, 5 * PP};
        jobs.j[6]  = {W_res_a + 16384,    128, 128, 6 * PP};
        jobs.j[7]  = {W_res_a + 32768,    128, 128, 7 * PP};
        jobs.j[8]  = {W_res_a + 49152,    128, 128, 8 * PP};
        jobs.j[9]  = {W_down,             128, 64,  OFF_DOWN};
        jobs.j[10] = {W_up,               64,  128, OFF_UP};
        dim3 g(64, 11);
        wprep_kernel<<<g, 256>>>(jobs);
    }
    conv_planes<<<(E * DD / 4 + 255) / 256, 256>>>(m_input, pm_h, pm_l, E * DD / 4);

    gemm_pp<128,128,true,true,false,false><<<grid, 1024, S11>>>(
        pm_h, pm_l, wp + 0 * PP, b_kj, nullptr, nullptr, rbf, wrbf,
        p0_h, p0_l, nullptr, E);
    gemm_pp<128,64,false,false,false,false><<<grid, 1024, S16>>>(
        p0_h, p0_l, wp + OFF_DOWN, nullptr, nullptr, nullptr, nullptr, nullptr,
        pxd_h, pxd_l, nullptr, E);
    triplet_kernel<<<(T + TPB_TRIP - 1) / TPB_TRIP, 256>>>(
        sbf, expand, reduce, W_sbf1, W_sbf2, pxd_h, pxd_l, agg, T);
    conv_planes<<<(E * DAA / 4 + 255) / 256, 256>>>(agg, pag_h, pag_l, E * DAA / 4);
    gemm_pp<64,128,false,false,false,false><<<grid, 1024, S61>>>(
        pag_h, pag_l, wp + OFF_UP, nullptr, nullptr, nullptr, nullptr, nullptr,
        p1_h, p1_l, nullptr, E);
    gemm_pp<128,128,false,true,true,false><<<grid, 1024, S11>>>(
        pm_h, pm_l, wp + 1 * PP, b_ji, p1_h, p1_l, nullptr, nullptr,
        p0_h, p0_l, nullptr, E);
    gemm_pp<128,128,false,true,false,false><<<grid, 1024, S11>>>(
        p0_h, p0_l, wp + 2 * PP, b_res_b, nullptr, nullptr, nullptr, nullptr,
        p1_h, p1_l, nullptr, E);
    gemm_pp<128,128,false,true,true,false><<<grid, 1024, S11>>>(
        p1_h, p1_l, wp + 3 * PP, b_res_b + DD, p0_h, p0_l, nullptr, nullptr,
        p1_h, p1_l, nullptr, E);
    gemm_pp<128,128,false,true,true,false><<<grid, 1024, S11>>>(
        p1_h, p1_l, wp + 4 * PP, b_final, pm_h, pm_l, nullptr, nullptr,
        p0_h, p0_l, nullptr, E);
    gemm_pp<128,128,false,true,false,false><<<grid, 1024, S11>>>(
        p0_h, p0_l, wp + 5 * PP, b_res_a, nullptr, nullptr, nullptr, nullptr,
        p1_h, p1_l, nullptr, E);
    gemm_pp<128,128,false,true,true,false><<<grid, 1024, S11>>>(
        p1_h, p1_l, wp + 6 * PP, b_res_a + DD, p0_h, p0_l, nullptr, nullptr,
        p1_h, p1_l, nullptr, E);
    gemm_pp<128,128,false,true,false,false><<<grid, 1024, S11>>>(
        p1_h, p1_l, wp + 7 * PP, b_res_a + 2 * DD, nullptr, nullptr, nullptr, nullptr,
        p0_h, p0_l, nullptr, E);
    gemm_pp<128,128,false,true,true,true><<<grid, 1024, S11>>>(
        p0_h, p0_l, wp + 8 * PP, b_res_a + 3 * DD, p1_h, p1_l, nullptr, nullptr,
        nullptr, nullptr, out, E);
}

// round 9
// speedup vs baseline: 2.3603x; 1.1867x over previous
#include <cuda_runtime.h>
#include <cuda_bf16.h>
#include <cstdint>

#define EMAX 262144
#define DD   128
#define DAA  64

// ---------------------------------------------------------------------------
// Device scratch (no allocations allowed)
// ---------------------------------------------------------------------------
__device__ __align__(256) unsigned char g_pm [(size_t)EMAX * DD * 4];  // m_input planes
__device__ __align__(256) unsigned char g_pxd[(size_t)EMAX * DAA * 4]; // xdown planes
__device__ __align__(256) unsigned char g_pag[(size_t)EMAX * DAA * 4]; // agg planes
__device__ float g_agg[(size_t)EMAX * DAA];
__device__ float g_wrbf[6 * DD];
__device__ __align__(256) unsigned char g_wplanes[1 << 20];            // weight hi/lo planes

// Weight plane layout constants (match wprep_kernel)
#define PP       69632                 // 128x128 hi/lo pair bytes (STR=272)
#define OFF_DOWN (9 * PP)              // W_down: NI=128, NO=64  -> 34816 B
#define OFF_UP   (OFF_DOWN + 34816)    // W_up:   NI=64,  NO=128 -> 36864 B

// smem layout for mega kernels
#define SOFF_GATE 0
#define SOFF_W    3072
#define SOFF_X    (SOFF_W + PP)
#define SOFF_T    (SOFF_X + PP)
#define SMEM_MEGA (SOFF_T + PP)        // 211968 bytes

// ---------------------------------------------------------------------------
// PTX helpers (plain sm_103-legal)
// ---------------------------------------------------------------------------
__device__ __forceinline__ uint32_t smem_u32(const void* p) {
    uint32_t a;
    asm("{ .reg .u64 t; cvta.to.shared.u64 t, %1; cvt.u32.u64 %0, t; }"
        : "=r"(a) : "l"(p));
    return a;
}
__device__ __forceinline__ void cp_async16(uint32_t dst, const void* src) {
    asm volatile("cp.async.cg.shared.global [%0], [%1], 16;" :: "r"(dst), "l"(src));
}
__device__ __forceinline__ void cp_commit() { asm volatile("cp.async.commit_group;"); }
__device__ __forceinline__ void cp_wait0()  { asm volatile("cp.async.wait_group 0;"); }

__device__ __forceinline__ void ldsm_x4(uint32_t& r0, uint32_t& r1,
                                        uint32_t& r2, uint32_t& r3, uint32_t addr) {
    asm volatile("ldmatrix.sync.aligned.m8n8.x4.shared.b16 {%0,%1,%2,%3}, [%4];"
                 : "=r"(r0), "=r"(r1), "=r"(r2), "=r"(r3) : "r"(addr));
}
__device__ __forceinline__ void mma_bf16(float* c, const uint32_t* a,
                                         uint32_t b0, uint32_t b1) {
    asm volatile(
        "mma.sync.aligned.m16n8k16.row.col.f32.bf16.bf16.f32 "
        "{%0,%1,%2,%3}, {%4,%5,%6,%7}, {%8,%9}, {%0,%1,%2,%3};"
        : "+f"(c[0]), "+f"(c[1]), "+f"(c[2]), "+f"(c[3])
        : "r"(a[0]), "r"(a[1]), "r"(a[2]), "r"(a[3]), "r"(b0), "r"(b1));
}
__device__ __forceinline__ uint32_t pk_bf2(__nv_bfloat16 a, __nv_bfloat16 b) {
    __nv_bfloat162 t(a, b);
    return *reinterpret_cast<uint32_t*>(&t);
}
__device__ __forceinline__ float swishf(float x) {
    return x * (1.0f / (1.0f + __expf(-x)));
}
__device__ __forceinline__ void red_add_v4(float* p, float4 v) {
    asm volatile("red.global.add.v4.f32 [%0], {%1, %2, %3, %4};"
                 :: "l"(p), "f"(v.x), "f"(v.y), "f"(v.z), "f"(v.w) : "memory");
}

// ---------------------------------------------------------------------------
// Utility kernels
// ---------------------------------------------------------------------------
__global__ void zero_kernel(float* __restrict__ p, int n4) {
    int i = blockIdx.x * blockDim.x + threadIdx.x;
    if (i < n4) *(float4*)&p[i * 4] = make_float4(0.f, 0.f, 0.f, 0.f);
}

__global__ void wrbf_kernel(const float* __restrict__ W1, const float* __restrict__ W2,
                            float* __restrict__ out) {
    int c = threadIdx.x;
    #pragma unroll
    for (int r = 0; r < 6; r++) {
        float s = 0.f;
        #pragma unroll
        for (int j = 0; j < 8; j++) s += W1[r * 8 + j] * W2[j * DD + c];
        out[r * DD + c] = s;
    }
}

__global__ void conv_planes(const float* __restrict__ in,
                            __nv_bfloat16* __restrict__ hi,
                            __nv_bfloat16* __restrict__ lo, int n4) {
    int i = blockIdx.x * blockDim.x + threadIdx.x;
    if (i >= n4) return;
    float4 v = *(const float4*)&in[i * 4];
    __nv_bfloat16 h0 = __float2bfloat16(v.x), h1 = __float2bfloat16(v.y);
    __nv_bfloat16 h2 = __float2bfloat16(v.z), h3 = __float2bfloat16(v.w);
    __nv_bfloat16 l0 = __float2bfloat16(v.x - __bfloat162float(h0));
    __nv_bfloat16 l1 = __float2bfloat16(v.y - __bfloat162float(h1));
    __nv_bfloat16 l2 = __float2bfloat16(v.z - __bfloat162float(h2));
    __nv_bfloat16 l3 = __float2bfloat16(v.w - __bfloat162float(h3));
    uint2 hv; hv.x = pk_bf2(h0, h1); hv.y = pk_bf2(h2, h3);
    uint2 lv; lv.x = pk_bf2(l0, l1); lv.y = pk_bf2(l2, l3);
    *(uint2*)&hi[i * 4] = hv;
    *(uint2*)&lo[i * 4] = lv;
}

struct WJob { const float* w; int ni, no, off; };
struct WJobs { WJob j[11]; };

__global__ void wprep_kernel(WJobs jobs) {
    WJob jb = jobs.j[blockIdx.y];
    const int STRb = jb.ni * 2 + 16;
    const int tot = jb.ni * jb.no;
    const int plane = jb.no * STRb;
    for (int i = blockIdx.x * blockDim.x + threadIdx.x; i < tot;
         i += gridDim.x * blockDim.x) {
        int k = i / jb.no, n = i % jb.no;
        float v = jb.w[i];
        __nv_bfloat16 h = __float2bfloat16(v);
        __nv_bfloat16 l = __float2bfloat16(v - __bfloat162float(h));
        unsigned char* base = g_wplanes + jb.off + n * STRb + k * 2;
        *(__nv_bfloat16*)base = h;
        *(__nv_bfloat16*)(base + plane) = l;
    }
}

// ---------------------------------------------------------------------------
// Fused-chain building blocks (1024 threads, 32 warps)
// ---------------------------------------------------------------------------
template <int NI>
__device__ __forceinline__ void load_act(uint32_t sb, int offA,
                                         const __nv_bfloat16* __restrict__ hi,
                                         const __nv_bfloat16* __restrict__ lo,
                                         int row0, int nrows, int tid) {
    constexpr int STR = NI * 2 + 16, NCH = NI / 8, TOT = 128 * NCH, APL = 128 * STR;
    #pragma unroll 2
    for (int i = tid; i < 2 * TOT; i += 1024) {
        int plane = (i >= TOT);
        int rem = plane ? i - TOT : i;
        int r = rem / NCH, ch = rem % NCH;
        int rr = row0 + r; if (rr >= nrows) rr = nrows - 1;
        const __nv_bfloat16* src = (plane ? lo : hi) + (size_t)rr * NI + ch * 8;
        cp_async16(sb + offA + plane * APL + r * STR + ch * 16, src);
    }
}

__device__ __forceinline__ void load_w(uint32_t sb, int offW,
                                       const unsigned char* __restrict__ src,
                                       int bytes, int tid) {
    #pragma unroll 4
    for (int i = tid * 16; i < bytes; i += 1024 * 16)
        cp_async16(sb + offW + i, src + i);
}

// MMA over one stage: acc += Ah*Bh + Ah*Bl + Al*Bh (fp32 frags).
template <int NI, int NO>
__device__ __forceinline__ void mma_stage(uint32_t sb, int offA, int offW,
                                          int w, int lane, float acc[NO / 32][4]) {
    constexpr int STR = NI * 2 + 16, APL = 128 * STR, BPL = NO * STR;
    constexpr int WN = NO / 4, NJ = WN / 8, NG = WN / 16;
    const int wm0 = (w & 7) * 16, wn0 = (w >> 3) * WN;
    const int lr = lane & 15, lk = (lane >> 4) * 8;
    #pragma unroll
    for (int nj = 0; nj < NJ; nj++)
        #pragma unroll
        for (int q = 0; q < 4; q++) acc[nj][q] = 0.f;
    #pragma unroll
    for (int pass = 0; pass < 3; pass++) {
        const uint32_t abase = sb + offA + (pass == 2 ? APL : 0);
        const uint32_t bbase = sb + offW + (pass == 1 ? BPL : 0);
        #pragma unroll
        for (int k0 = 0; k0 < NI; k0 += 16) {
            uint32_t a4[4];
            ldsm_x4(a4[0], a4[1], a4[2], a4[3],
                    abase + (uint32_t)((wm0 + lr) * STR + (k0 + lk) * 2));
            uint32_t b[NG][4];
            #pragma unroll
            for (int g = 0; g < NG; g++)
                ldsm_x4(b[g][0], b[g][1], b[g][2], b[g][3],
                        bbase + (uint32_t)((wn0 + g * 16 + lr) * STR + (k0 + lk) * 2));
            #pragma unroll
            for (int nj = 0; nj < NJ; nj++)
                mma_bf16(acc[nj], a4, b[nj >> 1][nj & 1], b[nj >> 1][(nj & 1) + 2]);
        }
    }
}

// Epilogue: bias -> swish -> [gate] -> [residual] -> out.
// RES: 0 none, 1 smem planes (128-wide, stride 272), 2 gmem fp32 (width NO)
// OUT: 0 smem planes (128-wide), 1 gmem bf planes (width NO), 2 gmem fp32
template <int NO, bool BIAS, bool GATE, int RES, int OUT>
__device__ __forceinline__ void stage_ep(char* smem, int offRes, int offOut,
                                         const float* __restrict__ bias,
                                         const float* __restrict__ rbf,
                                         int row0, int nrows,
                                         __nv_bfloat16* __restrict__ yh,
                                         __nv_bfloat16* __restrict__ yl,
                                         float* __restrict__ yf,
                                         const float* __restrict__ resf,
                                         int w, int lane, float acc[NO / 32][4]) {
    constexpr int NJ = NO / 32, WN = NO / 4;
    const int wm0 = (w & 7) * 16, wn0 = (w >> 3) * WN;
    const int sr = lane >> 2, sc = (lane & 3) * 2;
    #pragma unroll
    for (int half = 0; half < 2; half++) {
        const int r = wm0 + sr + half * 8;
        const int row = row0 + r;
        const int rclamp = (row < nrows) ? row : nrows - 1;
        float g6[6];
        if (GATE) {
            #pragma unroll
            for (int j = 0; j < 6; j++) g6[j] = rbf[(size_t)rclamp * 6 + j];
        }
        #pragma unroll
        for (int nj = 0; nj < NJ; nj++) {
            const int c = wn0 + nj * 8 + sc;
            float v0 = acc[nj][half * 2], v1 = acc[nj][half * 2 + 1];
            if (BIAS) { v0 += bias[c]; v1 += bias[c + 1]; }
            v0 = swishf(v0); v1 = swishf(v1);
            if (GATE) {
                float gg0 = 0.f, gg1 = 0.f;
                #pragma unroll
                for (int j = 0; j < 6; j++) {
                    gg0 += g6[j] * ((float*)smem)[j * 128 + c];
                    gg1 += g6[j] * ((float*)smem)[j * 128 + c + 1];
                }
                v0 *= gg0; v1 *= gg1;
            }
            if (RES == 1) {
                __nv_bfloat162 hh = *(__nv_bfloat162*)(smem + offRes + r * 272 + c * 2);
                __nv_bfloat162 ll = *(__nv_bfloat162*)(smem + offRes + 34816 + r * 272 + c * 2);
                float2 fh = __bfloat1622float2(hh), fl = __bfloat1622float2(ll);
                v0 += fh.x + fl.x; v1 += fh.y + fl.y;
            } else if (RES == 2) {
                float2 rv = *(const float2*)&resf[(size_t)rclamp * NO + c];
                v0 += rv.x; v1 += rv.y;
            }
            if (OUT == 2) {
                if (row < nrows)
                    *(float2*)&yf[(size_t)row * NO + c] = make_float2(v0, v1);
            } else {
                __nv_bfloat16 h0 = __float2bfloat16(v0), h1 = __float2bfloat16(v1);
                __nv_bfloat16 l0 = __float2bfloat16(v0 - __bfloat162float(h0));
                __nv_bfloat16 l1 = __float2bfloat16(v1 - __bfloat162float(h1));
                __nv_bfloat162 hv(h0, h1), lv(l0, l1);
                if (OUT == 0) {
                    *(__nv_bfloat162*)(smem + offOut + r * 272 + c * 2) = hv;
                    *(__nv_bfloat162*)(smem + offOut + 34816 + r * 272 + c * 2) = lv;
                } else if (row < nrows) {
                    *(__nv_bfloat162*)&yh[(size_t)row * NO + c] = hv;
                    *(__nv_bfloat162*)&yl[(size_t)row * NO + c] = lv;
                }
            }
        }
    }
}

// ---------------------------------------------------------------------------
// K1: fused  x = swish(m@W_kj+b)*gate ;  xdown = swish(x@W_down)
// ---------------------------------------------------------------------------
__global__ __launch_bounds__(1024, 1)
void mega_kj(const __nv_bfloat16* __restrict__ pm_h, const __nv_bfloat16* __restrict__ pm_l,
             const unsigned char* __restrict__ wp,
             const float* __restrict__ b_kj, const float* __restrict__ rbf,
             const float* __restrict__ wrbf,
             __nv_bfloat16* __restrict__ xd_h, __nv_bfloat16* __restrict__ xd_l,
             int nrows) {
    extern __shared__ char smem[];
    const uint32_t sb = smem_u32(smem);
    const int tid = threadIdx.x, w = tid >> 5, lane = tid & 31;

    for (int i = tid; i < 6 * 128; i += 1024) ((float*)smem)[i] = wrbf[i];

    const int ntiles = (nrows + 127) >> 7;
    for (int tile = blockIdx.x; tile < ntiles; tile += gridDim.x) {
        const int row0 = tile << 7;
        load_act<128>(sb, SOFF_X, pm_h, pm_l, row0, nrows, tid);
        load_w(sb, SOFF_W, wp + 0 * PP, PP, tid);
        cp_commit(); cp_wait0(); __syncthreads();

        float acc[4][4];
        mma_stage<128, 128>(sb, SOFF_X, SOFF_W, w, lane, acc);
        __syncthreads();
        load_w(sb, SOFF_W, wp + OFF_DOWN, 34816, tid); cp_commit();
        stage_ep<128, true, true, 0, 0>(smem, 0, SOFF_T, b_kj, rbf, row0, nrows,
                                        nullptr, nullptr, nullptr, nullptr, w, lane, acc);
        cp_wait0(); __syncthreads();

        float acc2[2][4];
        mma_stage<128, 64>(sb, SOFF_T, SOFF_W, w, lane, acc2);
        __syncthreads();
        stage_ep<64, false, false, 0, 1>(smem, 0, 0, nullptr, nullptr, row0, nrows,
                                         xd_h, xd_l, nullptr, nullptr, w, lane, acc2);
        __syncthreads();
    }
}

// ---------------------------------------------------------------------------
// K2: fused 9-GEMM chain:
//   p  = swish(agg@W_up)
//   m1 = swish(m@W_ji+b) + p
//   m2 = m1 + swish(swish(m1@Wb0+b)@Wb1+b)
//   m3 = swish(m2@W_final+b) + m_input
//   m4 = m3 + swish(swish(m3@Wa00+b)@Wa01+b)
//   out= m4 + swish(swish(m4@Wa10+b)@Wa11+b)
// ---------------------------------------------------------------------------
__global__ __launch_bounds__(1024, 1)
void mega_chain(const __nv_bfloat16* __restrict__ ag_h, const __nv_bfloat16* __restrict__ ag_l,
                const __nv_bfloat16* __restrict__ pm_h, const __nv_bfloat16* __restrict__ pm_l,
                const unsigned char* __restrict__ wp,
                const float* __restrict__ b_ji, const float* __restrict__ b_res_b,
                const float* __restrict__ b_final, const float* __restrict__ b_res_a,
                const float* __restrict__ m_input, float* __restrict__ out,
                int nrows) {
    extern __shared__ char smem[];
    const uint32_t sb = smem_u32(smem);
    const int tid = threadIdx.x, w = tid >> 5, lane = tid & 31;
    float acc[4][4];

    const int ntiles = (nrows + 127) >> 7;
    for (int tile = blockIdx.x; tile < ntiles; tile += gridDim.x) {
        const int row0 = tile << 7;

        // S1: p = swish(agg @ W_up)          A=X(agg,64)  out->T
        load_act<64>(sb, SOFF_X, ag_h, ag_l, row0, nrows, tid);
        load_w(sb, SOFF_W, wp + OFF_UP, 36864, tid);
        cp_commit(); cp_wait0(); __syncthreads();
        mma_stage<64, 128>(sb, SOFF_X, SOFF_W, w, lane, acc);
        __syncthreads();
        load_act<128>(sb, SOFF_X, pm_h, pm_l, row0, nrows, tid);
        load_w(sb, SOFF_W, wp + 1 * PP, PP, tid); cp_commit();
        stage_ep<128, false, false, 0, 0>(smem, 0, SOFF_T, nullptr, nullptr, row0, nrows,
                                          nullptr, nullptr, nullptr, nullptr, w, lane, acc);
        cp_wait0(); __syncthreads();

        // S2: m1 = swish(m@W_ji+b) + p       A=X(m)  res=T  out->T
        mma_stage<128, 128>(sb, SOFF_X, SOFF_W, w, lane, acc);
        __syncthreads();
        load_w(sb, SOFF_W, wp + 2 * PP, PP, tid); cp_commit();
        stage_ep<128, true, false, 1, 0>(smem, SOFF_T, SOFF_T, b_ji, nullptr, row0, nrows,
                                         nullptr, nullptr, nullptr, nullptr, w, lane, acc);
        cp_wait0(); __syncthreads();

        // S3: t = swish(m1@Wb0+b)            A=T  out->X
        mma_stage<128, 128>(sb, SOFF_T, SOFF_W, w, lane, acc);
        __syncthreads();
        load_w(sb, SOFF_W, wp + 3 * PP, PP, tid); cp_commit();
        stage_ep<128, true, false, 0, 0>(smem, 0, SOFF_X, b_res_b, nullptr, row0, nrows,
                                         nullptr, nullptr, nullptr, nullptr, w, lane, acc);
        cp_wait0(); __syncthreads();

        // S4: m2 = m1 + swish(t@Wb1+b)       A=X  res=T  out->T
        mma_stage<128, 128>(sb, SOFF_X, SOFF_W, w, lane, acc);
        __syncthreads();
        load_w(sb, SOFF_W, wp + 4 * PP, PP, tid); cp_commit();
        stage_ep<128, true, false, 1, 0>(smem, SOFF_T, SOFF_T, b_res_b + DD, nullptr, row0, nrows,
                                         nullptr, nullptr, nullptr, nullptr, w, lane, acc);
        cp_wait0(); __syncthreads();

        // S5: m3 = swish(m2@W_final+b) + m   A=T  res=gmem m_input  out->X
        mma_stage<128, 128>(sb, SOFF_T, SOFF_W, w, lane, acc);
        __syncthreads();
        load_w(sb, SOFF_W, wp + 5 * PP, PP, tid); cp_commit();
        stage_ep<128, true, false, 2, 0>(smem, 0, SOFF_X, b_final, nullptr, row0, nrows,
                                         nullptr, nullptr, nullptr, m_input, w, lane, acc);
        cp_wait0(); __syncthreads();

        // S6: t = swish(m3@Wa00+b)           A=X  out->T
        mma_stage<128, 128>(sb, SOFF_X, SOFF_W, w, lane, acc);
        __syncthreads();
        load_w(sb, SOFF_W, wp + 6 * PP, PP, tid); cp_commit();
        stage_ep<128, true, false, 0, 0>(smem, 0, SOFF_T, b_res_a, nullptr, row0, nrows,
                                         nullptr, nullptr, nullptr, nullptr, w, lane, acc);
        cp_wait0(); __syncthreads();

        // S7: m4 = m3 + swish(t@Wa01+b)      A=T  res=X  out->X
        mma_stage<128, 128>(sb, SOFF_T, SOFF_W, w, lane, acc);
        __syncthreads();
        load_w(sb, SOFF_W, wp + 7 * PP, PP, tid); cp_commit();
        stage_ep<128, true, false, 1, 0>(smem, SOFF_X, SOFF_X, b_res_a + DD, nullptr, row0, nrows,
                                         nullptr, nullptr, nullptr, nullptr, w, lane, acc);
        cp_wait0(); __syncthreads();

        // S8: t = swish(m4@Wa10+b)           A=X  out->T
        mma_stage<128, 128>(sb, SOFF_X, SOFF_W, w, lane, acc);
        __syncthreads();
        load_w(sb, SOFF_W, wp + 8 * PP, PP, tid); cp_commit();
        stage_ep<128, true, false, 0, 0>(smem, 0, SOFF_T, b_res_a + 2 * DD, nullptr, row0, nrows,
                                         nullptr, nullptr, nullptr, nullptr, w, lane, acc);
        cp_wait0(); __syncthreads();

        // S9: out = m4 + swish(t@Wa11+b)     A=T  res=X  out->gmem fp32
        mma_stage<128, 128>(sb, SOFF_T, SOFF_W, w, lane, acc);
        __syncthreads();
        stage_ep<128, true, false, 1, 2>(smem, SOFF_X, 0, b_res_a + 3 * DD, nullptr, row0, nrows,
                                         nullptr, nullptr, out, nullptr, w, lane, acc);
        __syncthreads();
    }
}

// ---------------------------------------------------------------------------
// Triplet kernel: gather xdown planes -> sbf gate -> vector atomic scatter
// ---------------------------------------------------------------------------
#define TPB_TRIP 64
__global__ __launch_bounds__(256)
void triplet_kernel(const float* __restrict__ sbf, const int* __restrict__ expand,
                    const int* __restrict__ reduce, const float* __restrict__ Wsbf1,
                    const float* __restrict__ Wsbf2,
                    const __nv_bfloat16* __restrict__ xh,
                    const __nv_bfloat16* __restrict__ xl,
                    float* __restrict__ agg, int Ttot) {
    __shared__ float s_sbf[TPB_TRIP * 42];
    __shared__ float s_h[TPB_TRIP * 9];
    __shared__ float s_w1[42 * 8];
    __shared__ float s_w2[8 * 64];
    __shared__ int   s_ekj[TPB_TRIP];
    __shared__ int   s_eji[TPB_TRIP];

    const int tid  = threadIdx.x;
    const int base = blockIdx.x * TPB_TRIP;
    const int n_t  = min(TPB_TRIP, Ttot - base);

    for (int i = tid; i < 42 * 8; i += 256) s_w1[i] = Wsbf1[i];
    for (int i = tid; i < 8 * 64; i += 256) s_w2[i] = Wsbf2[i];
    for (int i = tid; i < n_t * 42; i += 256) s_sbf[i] = sbf[(size_t)base * 42 + i];
    if (tid < n_t) {
        s_ekj[tid] = expand[base + tid];
        s_eji[tid] = reduce[base + tid];
    }
    __syncthreads();

    for (int wi = tid; wi < n_t * 8; wi += 256) {
        int i = wi >> 3, j = wi & 7;
        float s = 0.f;
        #pragma unroll
        for (int k = 0; k < 42; k++) s += s_sbf[i * 42 + k] * s_w1[k * 8 + j];
        s_h[i * 9 + j] = s;
    }
    __syncthreads();

    const int trip = tid >> 2;
    const int c0   = (tid & 3) * 16;
    if (trip < n_t) {
        float h[8];
        #pragma unroll
        for (int j = 0; j < 8; j++) h[j] = s_h[trip * 9 + j];
        const int ekj = s_ekj[trip];
        const int eji = s_eji[trip];
        const __nv_bfloat162* hp = (const __nv_bfloat162*)(xh + (size_t)ekj * DAA + c0);
        const __nv_bfloat162* lp = (const __nv_bfloat162*)(xl + (size_t)ekj * DAA + c0);
        float* ap = agg + (size_t)eji * DAA + c0;
        #pragma unroll
        for (int q = 0; q < 4; q++) {
            float2 ha = __bfloat1622float2(hp[2 * q]);
            float2 hb = __bfloat1622float2(hp[2 * q + 1]);
            float2 la = __bfloat1622float2(lp[2 * q]);
            float2 lb = __bfloat1622float2(lp[2 * q + 1]);
            float4 x = make_float4(ha.x + la.x, ha.y + la.y, hb.x + lb.x, hb.y + lb.y);
            int cb = c0 + q * 4;
            float g0 = 0.f, g1 = 0.f, g2 = 0.f, g3 = 0.f;
            #pragma unroll
            for (int j = 0; j < 8; j++) {
                float4 wv = *(const float4*)&s_w2[j * 64 + cb];
                float hj = h[j];
                g0 += hj * wv.x; g1 += hj * wv.y; g2 += hj * wv.z; g3 += hj * wv.w;
            }
            red_add_v4(ap + q * 4, make_float4(x.x * g0, x.y * g1, x.z * g2, x.w * g3));
        }
    }
}

// ---------------------------------------------------------------------------
// Host launcher
// ---------------------------------------------------------------------------
extern "C" void kernel_launch(void* const* d_in, const int* in_sizes, int n_in,
                              void* d_out, int out_size) {
    const float* m_input = (const float*)d_in[0];
    const float* rbf     = (const float*)d_in[1];
    const float* sbf     = (const float*)d_in[2];
    const int*   expand  = (const int*)d_in[3];
    const int*   reduce  = (const int*)d_in[4];
    const float* W_kj    = (const float*)d_in[5];
    const float* b_kj    = (const float*)d_in[6];
    const float* W_rbf1  = (const float*)d_in[7];
    const float* W_rbf2  = (const float*)d_in[8];
    const float* W_sbf1  = (const float*)d_in[9];
    const float* W_sbf2  = (const float*)d_in[10];
    const float* W_down  = (const float*)d_in[11];
    const float* W_up    = (const float*)d_in[12];
    const float* W_ji    = (const float*)d_in[13];
    const float* b_ji    = (const float*)d_in[14];
    const float* W_res_b = (const float*)d_in[15];
    const float* b_res_b = (const float*)d_in[16];
    const float* W_final = (const float*)d_in[17];
    const float* b_final = (const float*)d_in[18];
    const float* W_res_a = (const float*)d_in[19];
    const float* b_res_a = (const float*)d_in[20];
    float* out = (float*)d_out;

    const int E = in_sizes[0] / DD;
    const int T = in_sizes[3];

    unsigned char *pm, *pxd, *pag, *wp;
    float *agg, *wrbf;
    cudaGetSymbolAddress((void**)&pm,  g_pm);
    cudaGetSymbolAddress((void**)&pxd, g_pxd);
    cudaGetSymbolAddress((void**)&pag, g_pag);
    cudaGetSymbolAddress((void**)&agg, g_agg);
    cudaGetSymbolAddress((void**)&wrbf, g_wrbf);
    cudaGetSymbolAddress((void**)&wp,  g_wplanes);

    typedef __nv_bfloat16 bf;
    const size_t plD = (size_t)E * DD;
    const size_t plA = (size_t)E * DAA;
    bf *pm_h  = (bf*)pm,  *pm_l  = (bf*)pm  + plD;
    bf *pxd_h = (bf*)pxd, *pxd_l = (bf*)pxd + plA;
    bf *pag_h = (bf*)pag, *pag_l = (bf*)pag + plA;

    int smcnt = 148, dev = 0;
    cudaGetDevice(&dev);
    cudaDeviceGetAttribute(&smcnt, cudaDevAttrMultiProcessorCount, dev);
    const int ntiles = (E + 127) / 128;
    const int grid = (ntiles < smcnt) ? ntiles : smcnt;

    cudaFuncSetAttribute(mega_kj,    cudaFuncAttributeMaxDynamicSharedMemorySize, SMEM_MEGA);
    cudaFuncSetAttribute(mega_chain, cudaFuncAttributeMaxDynamicSharedMemorySize, SMEM_MEGA);

    // 0) zero agg, rbf-weight fuse, weight planes, m_input planes
    zero_kernel<<<(E * DAA / 4 + 255) / 256, 256>>>(agg, E * DAA / 4);
    wrbf_kernel<<<1, 128>>>(W_rbf1, W_rbf2, wrbf);
    {
        WJobs jobs;
        jobs.j[0]  = {W_kj,            128, 128, 0 * PP};
        jobs.j[1]  = {W_ji,            128, 128, 1 * PP};
        jobs.j[2]  = {W_res_b,         128, 128, 2 * PP};
        jobs.j[3]  = {W_res_b + 16384, 128, 128, 3 * PP};
        jobs.j[4]  = {W_final,         128, 128, 4 * PP};
        jobs.j[5]  = {W_res_a,         128, 128, 5 * PP};
        jobs.j[6]  = {W_res_a + 16384, 128, 128, 6 * PP};
        jobs.j[7]  = {W_res_a + 32768, 128, 128, 7 * PP};
        jobs.j[8]  = {W_res_a + 49152, 128, 128, 8 * PP};
        jobs.j[9]  = {W_down,          128, 64,  OFF_DOWN};
        jobs.j[10] = {W_up,            64,  128, OFF_UP};
        dim3 g(64, 11);
        wprep_kernel<<<g, 256>>>(jobs);
    }
    conv_planes<<<(E * DD / 4 + 255) / 256, 256>>>(m_input, pm_h, pm_l, E * DD / 4);

    // 1) fused kj+gate+down
    mega_kj<<<grid, 1024, SMEM_MEGA>>>(pm_h, pm_l, wp, b_kj, rbf, wrbf,
                                       pxd_h, pxd_l, E);
    // 2) triplet gather/gate/scatter
    triplet_kernel<<<(T + TPB_TRIP - 1) / TPB_TRIP, 256>>>(
        sbf, expand, reduce, W_sbf1, W_sbf2, pxd_h, pxd_l, agg, T);
    // 3) agg -> planes
    conv_planes<<<(E * DAA / 4 + 255) / 256, 256>>>(agg, pag_h, pag_l, E * DAA / 4);
    // 4) fused 9-GEMM chain -> out
    mega_chain<<<grid, 1024, SMEM_MEGA>>>(pag_h, pag_l, pm_h, pm_l, wp,
                                          b_ji, b_res_b, b_final, b_res_a,
                                          m_input, out, E);
}

// round 10
// speedup vs baseline: 4.4780x; 1.8973x over previous
#include <cuda_runtime.h>
#include <cuda_fp16.h>
#include <cstdint>

#define EMAX 262144
#define DD   128
#define DAA  64

// ---------------------------------------------------------------------------
// Device scratch (no allocations allowed)
// ---------------------------------------------------------------------------
__device__ __align__(256) unsigned char g_pm [(size_t)EMAX * DD * 4];
__device__ __align__(256) unsigned char g_pxd[(size_t)EMAX * DAA * 4];
__device__ __align__(256) unsigned char g_pag[(size_t)EMAX * DAA * 4];
__device__ float g_agg[(size_t)EMAX * DAA];
__device__ float g_wrbf[6 * DD];
__device__ __align__(256) unsigned char g_wplanes[1 << 20];   // fp16 hi/lo weight planes

// Weight plane layout (matches wprep_kernel): STR = NI*2+16
#define PP       69632                 // 128x128 hi+lo pair bytes (2*128*272)
#define OFF_DOWN (9 * PP)              // W_down pair: 2*64*272  = 34816
#define OFF_UP   (OFF_DOWN + 34816)    // W_up pair:   2*128*144 = 36864

// smem layout for mega kernels
#define SOFF_GATE 0
#define SOFF_W0   3072
#define SOFF_W1   (SOFF_W0 + PP)       // 72704
#define SOFF_X    (SOFF_W1 + PP)       // 142336  (128x128 fp16 act = 34816)
#define SOFF_T    (SOFF_X + 34816)     // 177152
#define SMEM_MEGA (SOFF_T + 34816)     // 211968

// ---------------------------------------------------------------------------
// PTX helpers (plain sm_103-legal)
// ---------------------------------------------------------------------------
__device__ __forceinline__ uint32_t smem_u32(const void* p) {
    uint32_t a;
    asm("{ .reg .u64 t; cvta.to.shared.u64 t, %1; cvt.u32.u64 %0, t; }"
        : "=r"(a) : "l"(p));
    return a;
}
__device__ __forceinline__ void cp_async16(uint32_t dst, const void* src) {
    asm volatile("cp.async.cg.shared.global [%0], [%1], 16;" :: "r"(dst), "l"(src));
}
__device__ __forceinline__ void cp_commit() { asm volatile("cp.async.commit_group;"); }
__device__ __forceinline__ void cp_wait0()  { asm volatile("cp.async.wait_group 0;"); }

__device__ __forceinline__ void ldsm_x4(uint32_t& r0, uint32_t& r1,
                                        uint32_t& r2, uint32_t& r3, uint32_t addr) {
    asm volatile("ldmatrix.sync.aligned.m8n8.x4.shared.b16 {%0,%1,%2,%3}, [%4];"
                 : "=r"(r0), "=r"(r1), "=r"(r2), "=r"(r3) : "r"(addr));
}
__device__ __forceinline__ void mma_f16(float* c, const uint32_t* a,
                                        uint32_t b0, uint32_t b1) {
    asm volatile(
        "mma.sync.aligned.m16n8k16.row.col.f32.f16.f16.f32 "
        "{%0,%1,%2,%3}, {%4,%5,%6,%7}, {%8,%9}, {%0,%1,%2,%3};"
        : "+f"(c[0]), "+f"(c[1]), "+f"(c[2]), "+f"(c[3])
        : "r"(a[0]), "r"(a[1]), "r"(a[2]), "r"(a[3]), "r"(b0), "r"(b1));
}
__device__ __forceinline__ float swishf(float x) {
    return x * (1.0f / (1.0f + __expf(-x)));
}
__device__ __forceinline__ void red_add_v4(float* p, float4 v) {
    asm volatile("red.global.add.v4.f32 [%0], {%1, %2, %3, %4};"
                 :: "l"(p), "f"(v.x), "f"(v.y), "f"(v.z), "f"(v.w) : "memory");
}

// ---------------------------------------------------------------------------
// Utility kernels
// ---------------------------------------------------------------------------
__global__ void zero_kernel(float* __restrict__ p, int n4) {
    int i = blockIdx.x * blockDim.x + threadIdx.x;
    if (i < n4) *(float4*)&p[i * 4] = make_float4(0.f, 0.f, 0.f, 0.f);
}

__global__ void wrbf_kernel(const float* __restrict__ W1, const float* __restrict__ W2,
                            float* __restrict__ out) {
    int c = threadIdx.x;
    #pragma unroll
    for (int r = 0; r < 6; r++) {
        float s = 0.f;
        #pragma unroll
        for (int j = 0; j < 8; j++) s += W1[r * 8 + j] * W2[j * DD + c];
        out[r * DD + c] = s;
    }
}

// fp32 -> fp16 (single plane), 8 elems per thread
__global__ void conv_half(const float* __restrict__ in, __half* __restrict__ outh, int n8) {
    int i = blockIdx.x * blockDim.x + threadIdx.x;
    if (i >= n8) return;
    const float4* p = (const float4*)&in[(size_t)i * 8];
    float4 a = p[0], b = p[1];
    __half2 h[4];
    h[0] = __halves2half2(__float2half_rn(a.x), __float2half_rn(a.y));
    h[1] = __halves2half2(__float2half_rn(a.z), __float2half_rn(a.w));
    h[2] = __halves2half2(__float2half_rn(b.x), __float2half_rn(b.y));
    h[3] = __halves2half2(__float2half_rn(b.z), __float2half_rn(b.w));
    *(uint4*)&outh[(size_t)i * 8] = *(uint4*)h;
}

// Weight prep: W [NI,NO] fp32 -> B^T fp16 hi plane + fp16 lo plane (residual)
struct WJob { const float* w; int ni, no, off; };
struct WJobs { WJob j[11]; };

__global__ void wprep_kernel(WJobs jobs) {
    WJob jb = jobs.j[blockIdx.y];
    const int STRb = jb.ni * 2 + 16;
    const int tot = jb.ni * jb.no;
    const int plane = jb.no * STRb;
    for (int i = blockIdx.x * blockDim.x + threadIdx.x; i < tot;
         i += gridDim.x * blockDim.x) {
        int k = i / jb.no, n = i % jb.no;
        float v = jb.w[i];
        __half h = __float2half_rn(v);
        __half l = __float2half_rn(v - __half2float(h));
        unsigned char* base = g_wplanes + jb.off + n * STRb + k * 2;
        *(__half*)base = h;
        *(__half*)(base + plane) = l;
    }
}

// ---------------------------------------------------------------------------
// Mega-kernel building blocks (1024 threads, 32 warps)
// ---------------------------------------------------------------------------
template <int NI>
__device__ __forceinline__ void load_act(uint32_t sb, uint32_t offA,
                                         const __half* __restrict__ src,
                                         int row0, int nrows, int tid) {
    constexpr int STR = NI * 2 + 16, NCH = NI / 8, TOT = 128 * NCH;
    #pragma unroll 2
    for (int i = tid; i < TOT; i += 1024) {
        int r = i / NCH, ch = i % NCH;
        int rr = row0 + r; if (rr >= nrows) rr = nrows - 1;
        cp_async16(sb + offA + r * STR + ch * 16, src + (size_t)rr * NI + ch * 8);
    }
}

__device__ __forceinline__ void load_w(uint32_t sb, uint32_t offW,
                                       const unsigned char* __restrict__ src,
                                       int bytes, int tid) {
    #pragma unroll 4
    for (int i = tid * 16; i < bytes; i += 1024 * 16)
        cp_async16(sb + offW + i, src + i);
}

// Fused 2-pass MMA: acc = A*Wh + A*Wl  (A fp16 single plane, W fp16 hi+lo)
template <int NI, int NO>
__device__ __forceinline__ void mma2(uint32_t sb, uint32_t offA, uint32_t offW,
                                     int w, int lane, float acc[NO / 32][4]) {
    constexpr int STR = NI * 2 + 16, BPL = NO * STR;
    constexpr int WN = NO / 4, NJ = WN / 8, NG = WN / 16;
    const int wm0 = (w & 7) * 16, wn0 = (w >> 3) * WN;
    const int lr = lane & 15, lk = (lane >> 4) * 8;
    #pragma unroll
    for (int nj = 0; nj < NJ; nj++)
        #pragma unroll
        for (int q = 0; q < 4; q++) acc[nj][q] = 0.f;
    #pragma unroll
    for (int k0 = 0; k0 < NI; k0 += 16) {
        uint32_t a4[4];
        ldsm_x4(a4[0], a4[1], a4[2], a4[3],
                sb + offA + (uint32_t)((wm0 + lr) * STR + (k0 + lk) * 2));
        uint32_t bh[NG][4], bl[NG][4];
        #pragma unroll
        for (int g = 0; g < NG; g++) {
            uint32_t ba = sb + offW + (uint32_t)((wn0 + g * 16 + lr) * STR + (k0 + lk) * 2);
            ldsm_x4(bh[g][0], bh[g][1], bh[g][2], bh[g][3], ba);
            ldsm_x4(bl[g][0], bl[g][1], bl[g][2], bl[g][3], ba + BPL);
        }
        #pragma unroll
        for (int nj = 0; nj < NJ; nj++)
            mma_f16(acc[nj], a4, bh[nj >> 1][nj & 1], bh[nj >> 1][(nj & 1) + 2]);
        #pragma unroll
        for (int nj = 0; nj < NJ; nj++)
            mma_f16(acc[nj], a4, bl[nj >> 1][nj & 1], bl[nj >> 1][(nj & 1) + 2]);
    }
}

// Epilogue: bias -> swish -> [gate] -> [residual] -> out.
// RES: 0 none, 1 smem fp16 (128-wide, stride 272), 2 gmem fp32 (width NO)
// OUT: 0 smem fp16 (128-wide), 1 gmem fp16 (width NO), 2 gmem fp32 (width NO)
template <int NO, bool BIAS, bool GATE, int RES, int OUT>
__device__ __forceinline__ void stage_ep2(char* smem, uint32_t offRes, uint32_t offOut,
                                          const float* __restrict__ bias,
                                          const float* __restrict__ rbf,
                                          int row0, int nrows,
                                          __half* __restrict__ yh,
                                          float* __restrict__ yf,
                                          const float* __restrict__ resf,
                                          int w, int lane, float acc[NO / 32][4]) {
    constexpr int NJ = NO / 32, WN = NO / 4;
    const int wm0 = (w & 7) * 16, wn0 = (w >> 3) * WN;
    const int sr = lane >> 2, sc = (lane & 3) * 2;
    #pragma unroll
    for (int hf = 0; hf < 2; hf++) {
        const int r = wm0 + sr + hf * 8;
        const int row = row0 + r;
        const int rc = (row < nrows) ? row : nrows - 1;
        float g6[6];
        if (GATE) {
            #pragma unroll
            for (int j = 0; j < 6; j++) g6[j] = rbf[(size_t)rc * 6 + j];
        }
        #pragma unroll
        for (int nj = 0; nj < NJ; nj++) {
            const int c = wn0 + nj * 8 + sc;
            float v0 = acc[nj][hf * 2], v1 = acc[nj][hf * 2 + 1];
            if (BIAS) { v0 += bias[c]; v1 += bias[c + 1]; }
            v0 = swishf(v0); v1 = swishf(v1);
            if (GATE) {
                float gg0 = 0.f, gg1 = 0.f;
                #pragma unroll
                for (int j = 0; j < 6; j++) {
                    gg0 += g6[j] * ((float*)smem)[j * 128 + c];
                    gg1 += g6[j] * ((float*)smem)[j * 128 + c + 1];
                }
                v0 *= gg0; v1 *= gg1;
            }
            if (RES == 1) {
                float2 f = __half22float2(*(__half2*)(smem + offRes + r * 272 + c * 2));
                v0 += f.x; v1 += f.y;
            } else if (RES == 2) {
                float2 rv = *(const float2*)&resf[(size_t)rc * NO + c];
                v0 += rv.x; v1 += rv.y;
            }
            if (OUT == 2) {
                if (row < nrows)
                    *(float2*)&yf[(size_t)row * NO + c] = make_float2(v0, v1);
            } else {
                __half2 hv = __halves2half2(__float2half_rn(v0), __float2half_rn(v1));
                if (OUT == 0)
                    *(__half2*)(smem + offOut + r * 272 + c * 2) = hv;
                else if (row < nrows)
                    *(__half2*)&yh[(size_t)row * NO + c] = hv;
            }
        }
    }
}

// ---------------------------------------------------------------------------
// K1: fused  x = swish(m@W_kj+b)*gate ;  xdown = swish(x@W_down)
// Weights loaded into smem ONCE per CTA (identical across tiles).
// ---------------------------------------------------------------------------
__global__ __launch_bounds__(1024, 1)
void mega_kj(const __half* __restrict__ pm,
             const unsigned char* __restrict__ wp,
             const float* __restrict__ b_kj, const float* __restrict__ rbf,
             const float* __restrict__ wrbf,
             __half* __restrict__ xd, int nrows) {
    extern __shared__ char smem[];
    const uint32_t sb = smem_u32(smem);
    const int tid = threadIdx.x, w = tid >> 5, lane = tid & 31;

    load_w(sb, SOFF_W0, wp + 0, PP, tid);
    load_w(sb, SOFF_W1, wp + OFF_DOWN, 34816, tid);
    cp_commit();
    for (int i = tid; i < 6 * 128; i += 1024) ((float*)smem)[i] = wrbf[i];

    float acc[4][4];
    float acc2[2][4];
    const int ntiles = (nrows + 127) >> 7;
    for (int tile = blockIdx.x; tile < ntiles; tile += gridDim.x) {
        const int row0 = tile << 7;
        load_act<128>(sb, SOFF_X, pm, row0, nrows, tid); cp_commit();
        cp_wait0(); __syncthreads();

        mma2<128, 128>(sb, SOFF_X, SOFF_W0, w, lane, acc);
        stage_ep2<128, true, true, 0, 0>(smem, 0, SOFF_T, b_kj, rbf, row0, nrows,
                                         nullptr, nullptr, nullptr, w, lane, acc);
        __syncthreads();

        mma2<128, 64>(sb, SOFF_T, SOFF_W1, w, lane, acc2);
        stage_ep2<64, false, false, 0, 1>(smem, 0, 0, nullptr, nullptr, row0, nrows,
                                          xd, nullptr, nullptr, w, lane, acc2);
        // no end-of-loop barrier needed: next load_act targets X, last read
        // before the mid-stage barrier above.
    }
}

// ---------------------------------------------------------------------------
// K2: fused 9-GEMM chain with double-buffered weights, 1 barrier per stage.
// ---------------------------------------------------------------------------
__global__ __launch_bounds__(1024, 1)
void mega_chain(const __half* __restrict__ ag, const __half* __restrict__ pm,
                const unsigned char* __restrict__ wp,
                const float* __restrict__ b_ji, const float* __restrict__ b_res_b,
                const float* __restrict__ b_final, const float* __restrict__ b_res_a,
                const float* __restrict__ m_input, float* __restrict__ out,
                int nrows) {
    extern __shared__ char smem[];
    const uint32_t sb = smem_u32(smem);
    const int tid = threadIdx.x, w = tid >> 5, lane = tid & 31;
    float acc[4][4];

    uint32_t wA = SOFF_W0, wB = SOFF_W1;   // wA = current stage's weights
    load_w(sb, wA, wp + OFF_UP, 36864, tid); cp_commit();

    const int ntiles = (nrows + 127) >> 7;
    for (int tile = blockIdx.x; tile < ntiles; tile += gridDim.x) {
        const int row0 = tile << 7;
        load_act<64>(sb, SOFF_X, ag, row0, nrows, tid); cp_commit();
        cp_wait0(); __syncthreads();

        // S1: p = swish(agg @ W_up)    in=X(agg) out=T
        mma2<64, 128>(sb, SOFF_X, wA, w, lane, acc);
        __syncthreads();  // X is about to be overwritten with pm
        load_act<128>(sb, SOFF_X, pm, row0, nrows, tid);
        load_w(sb, wB, wp + 1 * PP, PP, tid); cp_commit();
        stage_ep2<128, false, false, 0, 0>(smem, 0, SOFF_T, nullptr, nullptr, row0, nrows,
                                           nullptr, nullptr, nullptr, w, lane, acc);
        cp_wait0(); __syncthreads(); { uint32_t t = wA; wA = wB; wB = t; }

        // S2: m1 = swish(m@W_ji+b) + p      in=X res=T out=T
        mma2<128, 128>(sb, SOFF_X, wA, w, lane, acc);
        load_w(sb, wB, wp + 2 * PP, PP, tid); cp_commit();
        stage_ep2<128, true, false, 1, 0>(smem, SOFF_T, SOFF_T, b_ji, nullptr, row0, nrows,
                                          nullptr, nullptr, nullptr, w, lane, acc);
        cp_wait0(); __syncthreads(); { uint32_t t = wA; wA = wB; wB = t; }

        // S3: t = swish(m1@Wb0+b)           in=T out=X
        mma2<128, 128>(sb, SOFF_T, wA, w, lane, acc);
        load_w(sb, wB, wp + 3 * PP, PP, tid); cp_commit();
        stage_ep2<128, true, false, 0, 0>(smem, 0, SOFF_X, b_res_b, nullptr, row0, nrows,
                                          nullptr, nullptr, nullptr, w, lane, acc);
        cp_wait0(); __syncthreads(); { uint32_t t = wA; wA = wB; wB = t; }

        // S4: m2 = m1 + swish(t@Wb1+b)      in=X res=T out=T
        mma2<128, 128>(sb, SOFF_X, wA, w, lane, acc);
        load_w(sb, wB, wp + 4 * PP, PP, tid); cp_commit();
        stage_ep2<128, true, false, 1, 0>(smem, SOFF_T, SOFF_T, b_res_b + DD, nullptr, row0, nrows,
                                          nullptr, nullptr, nullptr, w, lane, acc);
        cp_wait0(); __syncthreads(); { uint32_t t = wA; wA = wB; wB = t; }

        // S5: m3 = swish(m2@W_final+b) + m  in=T res=gmem m_input out=X
        mma2<128, 128>(sb, SOFF_T, wA, w, lane, acc);
        load_w(sb, wB, wp + 5 * PP, PP, tid); cp_commit();
        stage_ep2<128, true, false, 2, 0>(smem, 0, SOFF_X, b_final, nullptr, row0, nrows,
                                          nullptr, nullptr, m_input, w, lane, acc);
        cp_wait0(); __syncthreads(); { uint32_t t = wA; wA = wB; wB = t; }

        // S6: t = swish(m3@Wa00+b)          in=X out=T
        mma2<128, 128>(sb, SOFF_X, wA, w, lane, acc);
        load_w(sb, wB, wp + 6 * PP, PP, tid); cp_commit();
        stage_ep2<128, true, false, 0, 0>(smem, 0, SOFF_T, b_res_a, nullptr, row0, nrows,
                                          nullptr, nullptr, nullptr, w, lane, acc);
        cp_wait0(); __syncthreads(); { uint32_t t = wA; wA = wB; wB = t; }

        // S7: m4 = m3 + swish(t@Wa01+b)     in=T res=X out=X
        mma2<128, 128>(sb, SOFF_T, wA, w, lane, acc);
        load_w(sb, wB, wp + 7 * PP, PP, tid); cp_commit();
        stage_ep2<128, true, false, 1, 0>(smem, SOFF_X, SOFF_X, b_res_a + DD, nullptr, row0, nrows,
                                          nullptr, nullptr, nullptr, w, lane, acc);
        cp_wait0(); __syncthreads(); { uint32_t t = wA; wA = wB; wB = t; }

        // S8: t = swish(m4@Wa10+b)          in=X out=T
        mma2<128, 128>(sb, SOFF_X, wA, w, lane, acc);
        load_w(sb, wB, wp + 8 * PP, PP, tid); cp_commit();
        stage_ep2<128, true, false, 0, 0>(smem, 0, SOFF_T, b_res_a + 2 * DD, nullptr, row0, nrows,
                                          nullptr, nullptr, nullptr, w, lane, acc);
        cp_wait0(); __syncthreads(); { uint32_t t = wA; wA = wB; wB = t; }

        // S9: out = m4 + swish(t@Wa11+b)    in=T res=X out=gmem fp32
        mma2<128, 128>(sb, SOFF_T, wA, w, lane, acc);
        load_w(sb, wB, wp + OFF_UP, 36864, tid); cp_commit();   // next tile's W_up
        stage_ep2<128, true, false, 1, 2>(smem, SOFF_X, 0, b_res_a + 3 * DD, nullptr, row0, nrows,
                                          nullptr, out, nullptr, w, lane, acc);
        cp_wait0(); __syncthreads(); { uint32_t t = wA; wA = wB; wB = t; }
    }
}

// ---------------------------------------------------------------------------
// Triplet kernel: gather xdown (fp16) -> sbf gate -> vector atomic scatter
// ---------------------------------------------------------------------------
#define TPB_TRIP 64
__global__ __launch_bounds__(256)
void triplet_kernel(const float* __restrict__ sbf, const int* __restrict__ expand,
                    const int* __restrict__ reduce, const float* __restrict__ Wsbf1,
                    const float* __restrict__ Wsbf2,
                    const __half* __restrict__ xh,
                    float* __restrict__ agg, int Ttot) {
    __shared__ float s_sbf[TPB_TRIP * 42];
    __shared__ float s_h[TPB_TRIP * 9];
    __shared__ float s_w1[42 * 8];
    __shared__ float s_w2[8 * 64];
    __shared__ int   s_ekj[TPB_TRIP];
    __shared__ int   s_eji[TPB_TRIP];

    const int tid  = threadIdx.x;
    const int base = blockIdx.x * TPB_TRIP;
    const int n_t  = min(TPB_TRIP, Ttot - base);

    for (int i = tid; i < 42 * 8; i += 256) s_w1[i] = Wsbf1[i];
    for (int i = tid; i < 8 * 64; i += 256) s_w2[i] = Wsbf2[i];
    for (int i = tid; i < n_t * 42; i += 256) s_sbf[i] = sbf[(size_t)base * 42 + i];
    if (tid < n_t) {
        s_ekj[tid] = expand[base + tid];
        s_eji[tid] = reduce[base + tid];
    }
    __syncthreads();

    for (int wi = tid; wi < n_t * 8; wi += 256) {
        int i = wi >> 3, j = wi & 7;
        float s = 0.f;
        #pragma unroll
        for (int k = 0; k < 42; k++) s += s_sbf[i * 42 + k] * s_w1[k * 8 + j];
        s_h[i * 9 + j] = s;
    }
    __syncthreads();

    const int trip = tid >> 2;
    const int c0   = (tid & 3) * 16;
    if (trip < n_t) {
        float h[8];
        #pragma unroll
        for (int j = 0; j < 8; j++) h[j] = s_h[trip * 9 + j];
        const int ekj = s_ekj[trip];
        const int eji = s_eji[trip];
        const uint4* xp = (const uint4*)(xh + (size_t)ekj * DAA + c0);
        uint4 u0 = xp[0], u1 = xp[1];
        float xs[16];
        {
            const __half2* ph = (const __half2*)&u0;
            #pragma unroll
            for (int j = 0; j < 4; j++) {
                float2 f = __half22float2(ph[j]);
                xs[2 * j] = f.x; xs[2 * j + 1] = f.y;
            }
            const __half2* pl = (const __half2*)&u1;
            #pragma unroll
            for (int j = 0; j < 4; j++) {
                float2 f = __half22float2(pl[j]);
                xs[8 + 2 * j] = f.x; xs[9 + 2 * j] = f.y;
            }
        }
        float* ap = agg + (size_t)eji * DAA + c0;
        #pragma unroll
        for (int q = 0; q < 4; q++) {
            int cb = c0 + q * 4;
            float g0 = 0.f, g1 = 0.f, g2 = 0.f, g3 = 0.f;
            #pragma unroll
            for (int j = 0; j < 8; j++) {
                float4 wv = *(const float4*)&s_w2[j * 64 + cb];
                float hj = h[j];
                g0 += hj * wv.x; g1 += hj * wv.y; g2 += hj * wv.z; g3 += hj * wv.w;
            }
            red_add_v4(ap + q * 4,
                       make_float4(xs[4 * q] * g0, xs[4 * q + 1] * g1,
                                   xs[4 * q + 2] * g2, xs[4 * q + 3] * g3));
        }
    }
}

// ---------------------------------------------------------------------------
// Host launcher
// ---------------------------------------------------------------------------
extern "C" void kernel_launch(void* const* d_in, const int* in_sizes, int n_in,
                              void* d_out, int out_size) {
    const float* m_input = (const float*)d_in[0];
    const float* rbf     = (const float*)d_in[1];
    const float* sbf     = (const float*)d_in[2];
    const int*   expand  = (const int*)d_in[3];
    const int*   reduce  = (const int*)d_in[4];
    const float* W_kj    = (const float*)d_in[5];
    const float* b_kj    = (const float*)d_in[6];
    const float* W_rbf1  = (const float*)d_in[7];
    const float* W_rbf2  = (const float*)d_in[8];
    const float* W_sbf1  = (const float*)d_in[9];
    const float* W_sbf2  = (const float*)d_in[10];
    const float* W_down  = (const float*)d_in[11];
    const float* W_up    = (const float*)d_in[12];
    const float* W_ji    = (const float*)d_in[13];
    const float* b_ji    = (const float*)d_in[14];
    const float* W_res_b = (const float*)d_in[15];
    const float* b_res_b = (const float*)d_in[16];
    const float* W_final = (const float*)d_in[17];
    const float* b_final = (const float*)d_in[18];
    const float* W_res_a = (const float*)d_in[19];
    const float* b_res_a = (const float*)d_in[20];
    float* out = (float*)d_out;

    const int E = in_sizes[0] / DD;
    const int T = in_sizes[3];

    unsigned char *pm, *pxd, *pag, *wp;
    float *agg, *wrbf;
    cudaGetSymbolAddress((void**)&pm,  g_pm);
    cudaGetSymbolAddress((void**)&pxd, g_pxd);
    cudaGetSymbolAddress((void**)&pag, g_pag);
    cudaGetSymbolAddress((void**)&agg, g_agg);
    cudaGetSymbolAddress((void**)&wrbf, g_wrbf);
    cudaGetSymbolAddress((void**)&wp,  g_wplanes);

    __half* pm_h  = (__half*)pm;
    __half* pxd_h = (__half*)pxd;
    __half* pag_h = (__half*)pag;

    int smcnt = 148, dev = 0;
    cudaGetDevice(&dev);
    cudaDeviceGetAttribute(&smcnt, cudaDevAttrMultiProcessorCount, dev);
    const int ntiles = (E + 127) / 128;
    const int grid = (ntiles < smcnt) ? ntiles : smcnt;

    cudaFuncSetAttribute(mega_kj,    cudaFuncAttributeMaxDynamicSharedMemorySize, SMEM_MEGA);
    cudaFuncSetAttribute(mega_chain, cudaFuncAttributeMaxDynamicSharedMemorySize, SMEM_MEGA);

    zero_kernel<<<(E * DAA / 4 + 255) / 256, 256>>>(agg, E * DAA / 4);
    wrbf_kernel<<<1, 128>>>(W_rbf1, W_rbf2, wrbf);
    {
        WJobs jobs;
        jobs.j[0]  = {W_kj,            128, 128, 0 * PP};
        jobs.j[1]  = {W_ji,            128, 128, 1 * PP};
        jobs.j[2]  = {W_res_b,         128, 128, 2 * PP};
        jobs.j[3]  = {W_res_b + 16384, 128, 128, 3 * PP};
        jobs.j[4]  = {W_final,         128, 128, 4 * PP};
        jobs.j[5]  = {W_res_a,         128, 128, 5 * PP};
        jobs.j[6]  = {W_res_a + 16384, 128, 128, 6 * PP};
        jobs.j[7]  = {W_res_a + 32768, 128, 128, 7 * PP};
        jobs.j[8]  = {W_res_a + 49152, 128, 128, 8 * PP};
        jobs.j[9]  = {W_down,          128, 64,  OFF_DOWN};
        jobs.j[10] = {W_up,            64,  128, OFF_UP};
        dim3 g(64, 11);
        wprep_kernel<<<g, 256>>>(jobs);
    }
    conv_half<<<(E * DD / 8 + 255) / 256, 256>>>(m_input, pm_h, E * DD / 8);

    mega_kj<<<grid, 1024, SMEM_MEGA>>>(pm_h, wp, b_kj, rbf, wrbf, pxd_h, E);

    triplet_kernel<<<(T + TPB_TRIP - 1) / TPB_TRIP, 256>>>(
        sbf, expand, reduce, W_sbf1, W_sbf2, pxd_h, agg, T);

    conv_half<<<(E * DAA / 8 + 255) / 256, 256>>>(agg, pag_h, E * DAA / 8);

    mega_chain<<<grid, 1024, SMEM_MEGA>>>(pag_h, pm_h, wp,
                                          b_ji, b_res_b, b_final, b_res_a,
                                          m_input, out, E);
}

// round 11
// speedup vs baseline: 4.8784x; 1.0894x over previous
#include <cuda_runtime.h>
#include <cuda_fp16.h>
#include <cstdint>

#define EMAX 262144
#define DD   128
#define DAA  64

// ---------------------------------------------------------------------------
// Device scratch (no allocations allowed)
// ---------------------------------------------------------------------------
__device__ __align__(256) unsigned char g_pm [(size_t)EMAX * DD * 4];   // m_input fp16
__device__ __align__(256) unsigned char g_pxd[(size_t)EMAX * DAA * 4];  // xdown fp16
__device__ __align__(256) unsigned char g_h  [(size_t)8 * EMAX * 8 * 2];// h = sbf@W1 fp16 (T x 8)
__device__ float g_agg[(size_t)EMAX * DAA];
__device__ float g_wrbf[6 * DD];
__device__ __align__(256) unsigned char g_wplanes[1 << 20];             // fp16 hi/lo weight planes

// Weight plane layout: STR = NI*2+16
#define PP       69632                 // 128x128 hi+lo pair bytes (2*128*272)
#define OFF_DOWN (9 * PP)
#define OFF_UP   (OFF_DOWN + 34816)

// smem layout for mega kernels
#define SOFF_GATE 0
#define SOFF_W0   3072
#define SOFF_W1   (SOFF_W0 + PP)
#define SOFF_X    (SOFF_W1 + PP)
#define SOFF_T    (SOFF_X + 34816)
#define SMEM_MEGA (SOFF_T + 34816)     // 211968

// ---------------------------------------------------------------------------
// PTX helpers
// ---------------------------------------------------------------------------
__device__ __forceinline__ uint32_t smem_u32(const void* p) {
    uint32_t a;
    asm("{ .reg .u64 t; cvta.to.shared.u64 t, %1; cvt.u32.u64 %0, t; }"
        : "=r"(a) : "l"(p));
    return a;
}
__device__ __forceinline__ void cp_async16(uint32_t dst, const void* src) {
    asm volatile("cp.async.cg.shared.global [%0], [%1], 16;" :: "r"(dst), "l"(src));
}
__device__ __forceinline__ void cp_commit() { asm volatile("cp.async.commit_group;"); }
__device__ __forceinline__ void cp_wait0()  { asm volatile("cp.async.wait_group 0;"); }

__device__ __forceinline__ void ldsm_x4(uint32_t& r0, uint32_t& r1,
                                        uint32_t& r2, uint32_t& r3, uint32_t addr) {
    asm volatile("ldmatrix.sync.aligned.m8n8.x4.shared.b16 {%0,%1,%2,%3}, [%4];"
                 : "=r"(r0), "=r"(r1), "=r"(r2), "=r"(r3) : "r"(addr));
}
__device__ __forceinline__ void mma_f16(float* c, const uint32_t* a,
                                        uint32_t b0, uint32_t b1) {
    asm volatile(
        "mma.sync.aligned.m16n8k16.row.col.f32.f16.f16.f32 "
        "{%0,%1,%2,%3}, {%4,%5,%6,%7}, {%8,%9}, {%0,%1,%2,%3};"
        : "+f"(c[0]), "+f"(c[1]), "+f"(c[2]), "+f"(c[3])
        : "r"(a[0]), "r"(a[1]), "r"(a[2]), "r"(a[3]), "r"(b0), "r"(b1));
}
__device__ __forceinline__ float swishf(float x) {
    return x * (1.0f / (1.0f + __expf(-x)));
}
__device__ __forceinline__ void red_add_v4(float* p, float4 v) {
    asm volatile("red.global.add.v4.f32 [%0], {%1, %2, %3, %4};"
                 :: "l"(p), "f"(v.x), "f"(v.y), "f"(v.z), "f"(v.w) : "memory");
}

// ---------------------------------------------------------------------------
// prep_all: one kernel for all preprocessing.
//   y in [0,10]: weight -> fp16 hi/lo B^T planes
//   y == 11: zero agg
//   y == 12: wrbf = W_rbf1 @ W_rbf2 (block x==0 only)
//   y == 13: m_input fp32 -> fp16
// ---------------------------------------------------------------------------
struct WJob { const float* w; int ni, no, off; };
struct WJobs { WJob j[11]; };

__global__ void prep_all(WJobs jobs,
                         const float* __restrict__ W1, const float* __restrict__ W2,
                         float* __restrict__ wrbf,
                         float* __restrict__ agg, int nAgg4,
                         const float* __restrict__ m_input, __half* __restrict__ pm,
                         int nM8) {
    const int tid = threadIdx.x;
    const int y = blockIdx.y;
    if (y < 11) {
        WJob jb = jobs.j[y];
        const int STRb = jb.ni * 2 + 16;
        const int tot = jb.ni * jb.no;
        const int plane = jb.no * STRb;
        for (int i = blockIdx.x * 256 + tid; i < tot; i += gridDim.x * 256) {
            int k = i / jb.no, n = i % jb.no;
            float v = jb.w[i];
            __half h = __float2half_rn(v);
            __half l = __float2half_rn(v - __half2float(h));
            unsigned char* base = g_wplanes + jb.off + n * STRb + k * 2;
            *(__half*)base = h;
            *(__half*)(base + plane) = l;
        }
    } else if (y == 11) {
        float4 z = make_float4(0.f, 0.f, 0.f, 0.f);
        for (int i = blockIdx.x * 256 + tid; i < nAgg4; i += gridDim.x * 256)
            *(float4*)&agg[(size_t)i * 4] = z;
    } else if (y == 12) {
        if (blockIdx.x == 0 && tid < 128) {
            int c = tid;
            #pragma unroll
            for (int r = 0; r < 6; r++) {
                float s = 0.f;
                #pragma unroll
                for (int j = 0; j < 8; j++) s += W1[r * 8 + j] * W2[j * DD + c];
                wrbf[r * DD + c] = s;
            }
        }
    } else {
        for (int i = blockIdx.x * 256 + tid; i < nM8; i += gridDim.x * 256) {
            const float4* p = (const float4*)&m_input[(size_t)i * 8];
            float4 a = p[0], b = p[1];
            __half2 h[4];
            h[0] = __halves2half2(__float2half_rn(a.x), __float2half_rn(a.y));
            h[1] = __halves2half2(__float2half_rn(a.z), __float2half_rn(a.w));
            h[2] = __halves2half2(__float2half_rn(b.x), __float2half_rn(b.y));
            h[3] = __halves2half2(__float2half_rn(b.z), __float2half_rn(b.w));
            *(uint4*)&pm[(size_t)i * 8] = *(uint4*)h;
        }
    }
}

// ---------------------------------------------------------------------------
// sbf_proj: h[t] = sbf[t] @ W_sbf1   (42 -> 8), fp16 out. Pure stream.
// 128 triplets / 256-thread block; block's sbf region is contiguous+16B aligned.
// ---------------------------------------------------------------------------
#define SP_TRIP 128
__global__ __launch_bounds__(256)
void sbf_proj(const float* __restrict__ sbf, const float* __restrict__ W1,
              __half* __restrict__ hout, int Ttot) {
    __shared__ float s_sbf[SP_TRIP * 42];
    __shared__ float s_w1[42 * 8];
    const uint32_t sbs = smem_u32(s_sbf);
    const int tid = threadIdx.x;
    const int base = blockIdx.x * SP_TRIP;
    const int n_t = min(SP_TRIP, Ttot - base);

    for (int i = tid; i < 336; i += 256) s_w1[i] = W1[i];
    if (n_t == SP_TRIP) {
        const char* src = (const char*)(sbf + (size_t)base * 42);
        #pragma unroll 2
        for (int i = tid; i < SP_TRIP * 42 * 4 / 16; i += 256)
            cp_async16(sbs + i * 16, src + i * 16);
        cp_commit(); cp_wait0();
    } else {
        for (int i = tid; i < n_t * 42; i += 256) s_sbf[i] = sbf[(size_t)base * 42 + i];
    }
    __syncthreads();

    const int i = tid >> 1, j0 = (tid & 1) * 4;
    if (i < n_t) {
        float hv[4] = {0.f, 0.f, 0.f, 0.f};
        const float* row = &s_sbf[i * 42];
        #pragma unroll
        for (int k = 0; k < 42; k++) {
            float sv = row[k];
            #pragma unroll
            for (int j = 0; j < 4; j++) hv[j] += sv * s_w1[k * 8 + j0 + j];
        }
        __half2 o[2];
        o[0] = __halves2half2(__float2half_rn(hv[0]), __float2half_rn(hv[1]));
        o[1] = __halves2half2(__float2half_rn(hv[2]), __float2half_rn(hv[3]));
        *(uint2*)&hout[(size_t)(base + i) * 8 + j0] = *(uint2*)o;
    }
}

// ---------------------------------------------------------------------------
// Mega-kernel building blocks (1024 threads, 32 warps)
// ---------------------------------------------------------------------------
template <int NI>
__device__ __forceinline__ void load_act(uint32_t sb, uint32_t offA,
                                         const __half* __restrict__ src,
                                         int row0, int nrows, int tid) {
    constexpr int STR = NI * 2 + 16, NCH = NI / 8, TOT = 128 * NCH;
    #pragma unroll 2
    for (int i = tid; i < TOT; i += 1024) {
        int r = i / NCH, ch = i % NCH;
        int rr = row0 + r; if (rr >= nrows) rr = nrows - 1;
        cp_async16(sb + offA + r * STR + ch * 16, src + (size_t)rr * NI + ch * 8);
    }
}

__device__ __forceinline__ void load_w(uint32_t sb, uint32_t offW,
                                       const unsigned char* __restrict__ src,
                                       int bytes, int tid) {
    #pragma unroll 4
    for (int i = tid * 16; i < bytes; i += 1024 * 16)
        cp_async16(sb + offW + i, src + i);
}

template <int NI, int NO>
__device__ __forceinline__ void mma2(uint32_t sb, uint32_t offA, uint32_t offW,
                                     int w, int lane, float acc[NO / 32][4]) {
    constexpr int STR = NI * 2 + 16, BPL = NO * STR;
    constexpr int WN = NO / 4, NJ = WN / 8, NG = WN / 16;
    const int wm0 = (w & 7) * 16, wn0 = (w >> 3) * WN;
    const int lr = lane & 15, lk = (lane >> 4) * 8;
    #pragma unroll
    for (int nj = 0; nj < NJ; nj++)
        #pragma unroll
        for (int q = 0; q < 4; q++) acc[nj][q] = 0.f;
    #pragma unroll
    for (int k0 = 0; k0 < NI; k0 += 16) {
        uint32_t a4[4];
        ldsm_x4(a4[0], a4[1], a4[2], a4[3],
                sb + offA + (uint32_t)((wm0 + lr) * STR + (k0 + lk) * 2));
        uint32_t bh[NG][4], bl[NG][4];
        #pragma unroll
        for (int g = 0; g < NG; g++) {
            uint32_t ba = sb + offW + (uint32_t)((wn0 + g * 16 + lr) * STR + (k0 + lk) * 2);
            ldsm_x4(bh[g][0], bh[g][1], bh[g][2], bh[g][3], ba);
            ldsm_x4(bl[g][0], bl[g][1], bl[g][2], bl[g][3], ba + BPL);
        }
        #pragma unroll
        for (int nj = 0; nj < NJ; nj++)
            mma_f16(acc[nj], a4, bh[nj >> 1][nj & 1], bh[nj >> 1][(nj & 1) + 2]);
        #pragma unroll
        for (int nj = 0; nj < NJ; nj++)
            mma_f16(acc[nj], a4, bl[nj >> 1][nj & 1], bl[nj >> 1][(nj & 1) + 2]);
    }
}

// Epilogue: bias -> swish -> [gate] -> [residual] -> out.
// RES: 0 none, 1 smem fp16 (stride 272), 2 gmem fp32 (width NO)
// OUT: 0 smem fp16 (stride 272), 1 gmem fp16 (width NO), 2 gmem fp32 (width NO)
template <int NO, bool BIAS, bool GATE, int RES, int OUT>
__device__ __forceinline__ void stage_ep2(char* smem, uint32_t offRes, uint32_t offOut,
                                          const float* __restrict__ bias,
                                          const float* __restrict__ rbf,
                                          int row0, int nrows,
                                          __half* __restrict__ yh,
                                          float* __restrict__ yf,
                                          const float* __restrict__ resf,
                                          int w, int lane, float acc[NO / 32][4]) {
    constexpr int NJ = NO / 32, WN = NO / 4;
    const int wm0 = (w & 7) * 16, wn0 = (w >> 3) * WN;
    const int sr = lane >> 2, sc = (lane & 3) * 2;
    #pragma unroll
    for (int hf = 0; hf < 2; hf++) {
        const int r = wm0 + sr + hf * 8;
        const int row = row0 + r;
        const int rc = (row < nrows) ? row : nrows - 1;
        float g6[6];
        if (GATE) {
            #pragma unroll
            for (int j = 0; j < 6; j++) g6[j] = rbf[(size_t)rc * 6 + j];
        }
        #pragma unroll
        for (int nj = 0; nj < NJ; nj++) {
            const int c = wn0 + nj * 8 + sc;
            float v0 = acc[nj][hf * 2], v1 = acc[nj][hf * 2 + 1];
            if (BIAS) { v0 += bias[c]; v1 += bias[c + 1]; }
            v0 = swishf(v0); v1 = swishf(v1);
            if (GATE) {
                float gg0 = 0.f, gg1 = 0.f;
                #pragma unroll
                for (int j = 0; j < 6; j++) {
                    gg0 += g6[j] * ((float*)smem)[j * 128 + c];
                    gg1 += g6[j] * ((float*)smem)[j * 128 + c + 1];
                }
                v0 *= gg0; v1 *= gg1;
            }
            if (RES == 1) {
                float2 f = __half22float2(*(__half2*)(smem + offRes + r * 272 + c * 2));
                v0 += f.x; v1 += f.y;
            } else if (RES == 2) {
                float2 rv = *(const float2*)&resf[(size_t)rc * NO + c];
                v0 += rv.x; v1 += rv.y;
            }
            if (OUT == 2) {
                if (row < nrows)
                    *(float2*)&yf[(size_t)row * NO + c] = make_float2(v0, v1);
            } else {
                __half2 hv = __halves2half2(__float2half_rn(v0), __float2half_rn(v1));
                if (OUT == 0)
                    *(__half2*)(smem + offOut + r * 272 + c * 2) = hv;
                else if (row < nrows)
                    *(__half2*)&yh[(size_t)row * NO + c] = hv;
            }
        }
    }
}

// ---------------------------------------------------------------------------
// mega_kj: x = swish(m@W_kj+b)*gate ; xdown = swish(x@W_down)
// ---------------------------------------------------------------------------
__global__ __launch_bounds__(1024, 1)
void mega_kj(const __half* __restrict__ pm,
             const unsigned char* __restrict__ wp,
             const float* __restrict__ b_kj, const float* __restrict__ rbf,
             const float* __restrict__ wrbf,
             __half* __restrict__ xd, int nrows) {
    extern __shared__ char smem[];
    const uint32_t sb = smem_u32(smem);
    const int tid = threadIdx.x, w = tid >> 5, lane = tid & 31;

    load_w(sb, SOFF_W0, wp + 0, PP, tid);
    load_w(sb, SOFF_W1, wp + OFF_DOWN, 34816, tid);
    cp_commit();
    for (int i = tid; i < 6 * 128; i += 1024) ((float*)smem)[i] = wrbf[i];

    float acc[4][4];
    float acc2[2][4];
    const int ntiles = (nrows + 127) >> 7;
    for (int tile = blockIdx.x; tile < ntiles; tile += gridDim.x) {
        const int row0 = tile << 7;
        load_act<128>(sb, SOFF_X, pm, row0, nrows, tid); cp_commit();
        cp_wait0(); __syncthreads();

        mma2<128, 128>(sb, SOFF_X, SOFF_W0, w, lane, acc);
        stage_ep2<128, true, true, 0, 0>(smem, 0, SOFF_T, b_kj, rbf, row0, nrows,
                                         nullptr, nullptr, nullptr, w, lane, acc);
        __syncthreads();

        mma2<128, 64>(sb, SOFF_T, SOFF_W1, w, lane, acc2);
        stage_ep2<64, false, false, 0, 1>(smem, 0, 0, nullptr, nullptr, row0, nrows,
                                          xd, nullptr, nullptr, w, lane, acc2);
    }
}

// ---------------------------------------------------------------------------
// triplet2: gather xdown fp16 + h fp16 -> g = h@W_sbf2 gate -> atomic scatter
// ---------------------------------------------------------------------------
#define TPB_TRIP 64
__global__ __launch_bounds__(256)
void triplet2(const int* __restrict__ expand, const int* __restrict__ reduce,
              const float* __restrict__ Wsbf2,
              const __half* __restrict__ hin, const __half* __restrict__ xh,
              float* __restrict__ agg, int Ttot) {
    __shared__ float s_h[TPB_TRIP * 9];
    __shared__ float s_w2[8 * 64];
    __shared__ int   s_ekj[TPB_TRIP];
    __shared__ int   s_eji[TPB_TRIP];

    const int tid  = threadIdx.x;
    const int base = blockIdx.x * TPB_TRIP;
    const int n_t  = min(TPB_TRIP, Ttot - base);

    for (int i = tid; i < 512; i += 256) s_w2[i] = Wsbf2[i];
    if (tid < n_t) {
        s_ekj[tid] = expand[base + tid];
        s_eji[tid] = reduce[base + tid];
        uint4 hv = *(const uint4*)&hin[(size_t)(base + tid) * 8];
        const __half2* hp = (const __half2*)&hv;
        #pragma unroll
        for (int j = 0; j < 4; j++) {
            float2 f = __half22float2(hp[j]);
            s_h[tid * 9 + 2 * j] = f.x;
            s_h[tid * 9 + 2 * j + 1] = f.y;
        }
    }
    __syncthreads();

    const int trip = tid >> 2;
    const int c0   = (tid & 3) * 16;
    if (trip < n_t) {
        float h[8];
        #pragma unroll
        for (int j = 0; j < 8; j++) h[j] = s_h[trip * 9 + j];
        const int ekj = s_ekj[trip];
        const int eji = s_eji[trip];
        const uint4* xp = (const uint4*)(xh + (size_t)ekj * DAA + c0);
        uint4 u0 = xp[0], u1 = xp[1];
        float xs[16];
        {
            const __half2* ph = (const __half2*)&u0;
            #pragma unroll
            for (int j = 0; j < 4; j++) {
                float2 f = __half22float2(ph[j]);
                xs[2 * j] = f.x; xs[2 * j + 1] = f.y;
            }
            const __half2* pl = (const __half2*)&u1;
            #pragma unroll
            for (int j = 0; j < 4; j++) {
                float2 f = __half22float2(pl[j]);
                xs[8 + 2 * j] = f.x; xs[9 + 2 * j] = f.y;
            }
        }
        float* ap = agg + (size_t)eji * DAA + c0;
        #pragma unroll
        for (int q = 0; q < 4; q++) {
            int cb = c0 + q * 4;
            float g0 = 0.f, g1 = 0.f, g2 = 0.f, g3 = 0.f;
            #pragma unroll
            for (int j = 0; j < 8; j++) {
                float4 wv = *(const float4*)&s_w2[j * 64 + cb];
                float hj = h[j];
                g0 += hj * wv.x; g1 += hj * wv.y; g2 += hj * wv.z; g3 += hj * wv.w;
            }
            red_add_v4(ap + q * 4,
                       make_float4(xs[4 * q] * g0, xs[4 * q + 1] * g1,
                                   xs[4 * q + 2] * g2, xs[4 * q + 3] * g3));
        }
    }
}

// ---------------------------------------------------------------------------
// mega_chain: fused 9-GEMM chain; S1 reads agg fp32 directly.
// ---------------------------------------------------------------------------
__global__ __launch_bounds__(1024, 1)
void mega_chain(const float* __restrict__ aggf, const __half* __restrict__ pm,
                const unsigned char* __restrict__ wp,
                const float* __restrict__ b_ji, const float* __restrict__ b_res_b,
                const float* __restrict__ b_final, const float* __restrict__ b_res_a,
                const float* __restrict__ m_input, float* __restrict__ out,
                int nrows) {
    extern __shared__ char smem[];
    const uint32_t sb = smem_u32(smem);
    const int tid = threadIdx.x, w = tid >> 5, lane = tid & 31;
    float acc[4][4];

    uint32_t wA = SOFF_W0, wB = SOFF_W1;
    load_w(sb, wA, wp + OFF_UP, 36864, tid); cp_commit();

    const int ntiles = (nrows + 127) >> 7;
    for (int tile = blockIdx.x; tile < ntiles; tile += gridDim.x) {
        const int row0 = tile << 7;

        // agg fp32 -> fp16 smem X (STR=144); 1024 threads cover 128x64
        {
            int r = tid >> 3, c0 = (tid & 7) * 8;
            int rr = row0 + r; if (rr >= nrows) rr = nrows - 1;
            float4 a = *(const float4*)&aggf[(size_t)rr * DAA + c0];
            float4 b = *(const float4*)&aggf[(size_t)rr * DAA + c0 + 4];
            __half2 hh[4];
            hh[0] = __halves2half2(__float2half_rn(a.x), __float2half_rn(a.y));
            hh[1] = __halves2half2(__float2half_rn(a.z), __float2half_rn(a.w));
            hh[2] = __halves2half2(__float2half_rn(b.x), __float2half_rn(b.y));
            hh[3] = __halves2half2(__float2half_rn(b.z), __float2half_rn(b.w));
            *(uint4*)(smem + SOFF_X + r * 144 + c0 * 2) = *(uint4*)hh;
        }
        cp_wait0(); __syncthreads();

        // S1: p = swish(agg @ W_up)    in=X(agg,64) out=T
        mma2<64, 128>(sb, SOFF_X, wA, w, lane, acc);
        __syncthreads();
        load_act<128>(sb, SOFF_X, pm, row0, nrows, tid);
        load_w(sb, wB, wp + 1 * PP, PP, tid); cp_commit();
        stage_ep2<128, false, false, 0, 0>(smem, 0, SOFF_T, nullptr, nullptr, row0, nrows,
                                           nullptr, nullptr, nullptr, w, lane, acc);
        cp_wait0(); __syncthreads(); { uint32_t t = wA; wA = wB; wB = t; }

        // S2: m1 = swish(m@W_ji+b) + p
        mma2<128, 128>(sb, SOFF_X, wA, w, lane, acc);
        load_w(sb, wB, wp + 2 * PP, PP, tid); cp_commit();
        stage_ep2<128, true, false, 1, 0>(smem, SOFF_T, SOFF_T, b_ji, nullptr, row0, nrows,
                                          nullptr, nullptr, nullptr, w, lane, acc);
        cp_wait0(); __syncthreads(); { uint32_t t = wA; wA = wB; wB = t; }

        // S3: t = swish(m1@Wb0+b)
        mma2<128, 128>(sb, SOFF_T, wA, w, lane, acc);
        load_w(sb, wB, wp + 3 * PP, PP, tid); cp_commit();
        stage_ep2<128, true, false, 0, 0>(smem, 0, SOFF_X, b_res_b, nullptr, row0, nrows,
                                          nullptr, nullptr, nullptr, w, lane, acc);
        cp_wait0(); __syncthreads(); { uint32_t t = wA; wA = wB; wB = t; }

        // S4: m2 = m1 + swish(t@Wb1+b)
        mma2<128, 128>(sb, SOFF_X, wA, w, lane, acc);
        load_w(sb, wB, wp + 4 * PP, PP, tid); cp_commit();
        stage_ep2<128, true, false, 1, 0>(smem, SOFF_T, SOFF_T, b_res_b + DD, nullptr, row0, nrows,
                                          nullptr, nullptr, nullptr, w, lane, acc);
        cp_wait0(); __syncthreads(); { uint32_t t = wA; wA = wB; wB = t; }

        // S5: m3 = swish(m2@W_final+b) + m_input
        mma2<128, 128>(sb, SOFF_T, wA, w, lane, acc);
        load_w(sb, wB, wp + 5 * PP, PP, tid); cp_commit();
        stage_ep2<128, true, false, 2, 0>(smem, 0, SOFF_X, b_final, nullptr, row0, nrows,
                                          nullptr, nullptr, m_input, w, lane, acc);
        cp_wait0(); __syncthreads(); { uint32_t t = wA; wA = wB; wB = t; }

        // S6: t = swish(m3@Wa00+b)
        mma2<128, 128>(sb, SOFF_X, wA, w, lane, acc);
        load_w(sb, wB, wp + 6 * PP, PP, tid); cp_commit();
        stage_ep2<128, true, false, 0, 0>(smem, 0, SOFF_T, b_res_a, nullptr, row0, nrows,
                                          nullptr, nullptr, nullptr, w, lane, acc);
        cp_wait0(); __syncthreads(); { uint32_t t = wA; wA = wB; wB = t; }

        // S7: m4 = m3 + swish(t@Wa01+b)
        mma2<128, 128>(sb, SOFF_T, wA, w, lane, acc);
        load_w(sb, wB, wp + 7 * PP, PP, tid); cp_commit();
        stage_ep2<128, true, false, 1, 0>(smem, SOFF_X, SOFF_X, b_res_a + DD, nullptr, row0, nrows,
                                          nullptr, nullptr, nullptr, w, lane, acc);
        cp_wait0(); __syncthreads(); { uint32_t t = wA; wA = wB; wB = t; }

        // S8: t = swish(m4@Wa10+b)
        mma2<128, 128>(sb, SOFF_X, wA, w, lane, acc);
        load_w(sb, wB, wp + 8 * PP, PP, tid); cp_commit();
        stage_ep2<128, true, false, 0, 0>(smem, 0, SOFF_T, b_res_a + 2 * DD, nullptr, row0, nrows,
                                          nullptr, nullptr, nullptr, w, lane, acc);
        cp_wait0(); __syncthreads(); { uint32_t t = wA; wA = wB; wB = t; }

        // S9: out = m4 + swish(t@Wa11+b)  -> gmem fp32
        mma2<128, 128>(sb, SOFF_T, wA, w, lane, acc);
        load_w(sb, wB, wp + OFF_UP, 36864, tid); cp_commit();   // next tile's W_up
        stage_ep2<128, true, false, 1, 2>(smem, SOFF_X, 0, b_res_a + 3 * DD, nullptr, row0, nrows,
                                          nullptr, out, nullptr, w, lane, acc);
        cp_wait0(); __syncthreads(); { uint32_t t = wA; wA = wB; wB = t; }
    }
}

// ---------------------------------------------------------------------------
// Host launcher — 5 launches; triplet2 is 4th (ncu capture slot).
// ---------------------------------------------------------------------------
extern "C" void kernel_launch(void* const* d_in, const int* in_sizes, int n_in,
                              void* d_out, int out_size) {
    const float* m_input = (const float*)d_in[0];
    const float* rbf     = (const float*)d_in[1];
    const float* sbf     = (const float*)d_in[2];
    const int*   expand  = (const int*)d_in[3];
    const int*   reduce  = (const int*)d_in[4];
    const float* W_kj    = (const float*)d_in[5];
    const float* b_kj    = (const float*)d_in[6];
    const float* W_rbf1  = (const float*)d_in[7];
    const float* W_rbf2  = (const float*)d_in[8];
    const float* W_sbf1  = (const float*)d_in[9];
    const float* W_sbf2  = (const float*)d_in[10];
    const float* W_down  = (const float*)d_in[11];
    const float* W_up    = (const float*)d_in[12];
    const float* W_ji    = (const float*)d_in[13];
    const float* b_ji    = (const float*)d_in[14];
    const float* W_res_b = (const float*)d_in[15];
    const float* b_res_b = (const float*)d_in[16];
    const float* W_final = (const float*)d_in[17];
    const float* b_final = (const float*)d_in[18];
    const float* W_res_a = (const float*)d_in[19];
    const float* b_res_a = (const float*)d_in[20];
    float* out = (float*)d_out;

    const int E = in_sizes[0] / DD;
    const int T = in_sizes[3];

    unsigned char *pm, *pxd, *ph, *wp;
    float *agg, *wrbf;
    cudaGetSymbolAddress((void**)&pm,  g_pm);
    cudaGetSymbolAddress((void**)&pxd, g_pxd);
    cudaGetSymbolAddress((void**)&ph,  g_h);
    cudaGetSymbolAddress((void**)&agg, g_agg);
    cudaGetSymbolAddress((void**)&wrbf, g_wrbf);
    cudaGetSymbolAddress((void**)&wp,  g_wplanes);

    __half* pm_h  = (__half*)pm;
    __half* pxd_h = (__half*)pxd;
    __half* h_buf = (__half*)ph;

    int smcnt = 148, dev = 0;
    cudaGetDevice(&dev);
    cudaDeviceGetAttribute(&smcnt, cudaDevAttrMultiProcessorCount, dev);
    const int ntiles = (E + 127) / 128;
    const int grid = (ntiles < smcnt) ? ntiles : smcnt;

    cudaFuncSetAttribute(mega_kj,    cudaFuncAttributeMaxDynamicSharedMemorySize, SMEM_MEGA);
    cudaFuncSetAttribute(mega_chain, cudaFuncAttributeMaxDynamicSharedMemorySize, SMEM_MEGA);

    // 1) all preprocessing in one kernel
    {
        WJobs jobs;
        jobs.j[0]  = {W_kj,            128, 128, 0 * PP};
        jobs.j[1]  = {W_ji,            128, 128, 1 * PP};
        jobs.j[2]  = {W_res_b,         128, 128, 2 * PP};
        jobs.j[3]  = {W_res_b + 16384, 128, 128, 3 * PP};
        jobs.j[4]  = {W_final,         128, 128, 4 * PP};
        jobs.j[5]  = {W_res_a,         128, 128, 5 * PP};
        jobs.j[6]  = {W_res_a + 16384, 128, 128, 6 * PP};
        jobs.j[7]  = {W_res_a + 32768, 128, 128, 7 * PP};
        jobs.j[8]  = {W_res_a + 49152, 128, 128, 8 * PP};
        jobs.j[9]  = {W_down,          128, 64,  OFF_DOWN};
        jobs.j[10] = {W_up,            64,  128, OFF_UP};
        dim3 g(256, 14);
        prep_all<<<g, 256>>>(jobs, W_rbf1, W_rbf2, wrbf,
                             agg, E * DAA / 4, m_input, pm_h, E * DD / 8);
    }
    // 2) h = sbf @ W_sbf1 (fp16)
    sbf_proj<<<(T + SP_TRIP - 1) / SP_TRIP, 256>>>(sbf, W_sbf1, h_buf, T);
    // 3) fused kj+gate+down
    mega_kj<<<grid, 1024, SMEM_MEGA>>>(pm_h, wp, b_kj, rbf, wrbf, pxd_h, E);
    // 4) triplet gather/gate/scatter  (ncu capture slot)
    triplet2<<<(T + TPB_TRIP - 1) / TPB_TRIP, 256>>>(
        expand, reduce, W_sbf2, h_buf, pxd_h, agg, T);
    // 5) fused 9-GEMM chain -> out
    mega_chain<<<grid, 1024, SMEM_MEGA>>>(agg, pm_h, wp,
                                          b_ji, b_res_b, b_final, b_res_a,
                                          m_input, out, E);
}

// round 12
// speedup vs baseline: 5.3500x; 1.0967x over previous
#include <cuda_runtime.h>
#include <cuda_fp16.h>
#include <cstdint>

#define EMAX 262144
#define DD   128
#define DAA  64

// ---------------------------------------------------------------------------
// Device scratch (no allocations allowed)
// ---------------------------------------------------------------------------
__device__ __align__(256) unsigned char g_pm [(size_t)EMAX * DD * 4];   // m_input fp16
__device__ __align__(256) unsigned char g_pxd[(size_t)EMAX * DAA * 4];  // xdown fp16
__device__ __align__(256) unsigned char g_h  [(size_t)8 * EMAX * 8 * 2];// h = sbf@W1 fp16 (T x 8)
__device__ float g_agg[(size_t)EMAX * DAA];
__device__ float g_wrbf[6 * DD];
__device__ __align__(256) unsigned char g_wplanes[1 << 20];             // fp16 hi/lo weight planes

// Weight plane layout: STR = NI*2+16
#define PP       69632                 // 128x128 hi+lo pair bytes (2*128*272)
#define OFF_DOWN (9 * PP)
#define OFF_UP   (OFF_DOWN + 34816)

// smem layout for mega kernels
#define SOFF_GATE 0
#define SOFF_W0   3072
#define SOFF_W1   (SOFF_W0 + PP)
#define SOFF_X    (SOFF_W1 + PP)
#define SOFF_T    (SOFF_X + 34816)
#define SMEM_MEGA (SOFF_T + 34816)     // 211968

// ---------------------------------------------------------------------------
// PTX helpers
// ---------------------------------------------------------------------------
__device__ __forceinline__ uint32_t smem_u32(const void* p) {
    uint32_t a;
    asm("{ .reg .u64 t; cvta.to.shared.u64 t, %1; cvt.u32.u64 %0, t; }"
        : "=r"(a) : "l"(p));
    return a;
}
__device__ __forceinline__ void cp_async16(uint32_t dst, const void* src) {
    asm volatile("cp.async.cg.shared.global [%0], [%1], 16;" :: "r"(dst), "l"(src));
}
__device__ __forceinline__ void cp_commit() { asm volatile("cp.async.commit_group;"); }
__device__ __forceinline__ void cp_wait0()  { asm volatile("cp.async.wait_group 0;"); }

__device__ __forceinline__ void ldsm_x4(uint32_t& r0, uint32_t& r1,
                                        uint32_t& r2, uint32_t& r3, uint32_t addr) {
    asm volatile("ldmatrix.sync.aligned.m8n8.x4.shared.b16 {%0,%1,%2,%3}, [%4];"
                 : "=r"(r0), "=r"(r1), "=r"(r2), "=r"(r3) : "r"(addr));
}
__device__ __forceinline__ void mma_f16(float* c, const uint32_t* a,
                                        uint32_t b0, uint32_t b1) {
    asm volatile(
        "mma.sync.aligned.m16n8k16.row.col.f32.f16.f16.f32 "
        "{%0,%1,%2,%3}, {%4,%5,%6,%7}, {%8,%9}, {%0,%1,%2,%3};"
        : "+f"(c[0]), "+f"(c[1]), "+f"(c[2]), "+f"(c[3])
        : "r"(a[0]), "r"(a[1]), "r"(a[2]), "r"(a[3]), "r"(b0), "r"(b1));
}
__device__ __forceinline__ float swishf(float x) {
    return x * (1.0f / (1.0f + __expf(-x)));
}
__device__ __forceinline__ void red_add_v4(float* p, float4 v) {
    asm volatile("red.global.add.v4.f32 [%0], {%1, %2, %3, %4};"
                 :: "l"(p), "f"(v.x), "f"(v.y), "f"(v.z), "f"(v.w) : "memory");
}

// ---------------------------------------------------------------------------
// prep_all: all preprocessing in one kernel (grid.y jobs)
// ---------------------------------------------------------------------------
struct WJob { const float* w; int ni, no, off; };
struct WJobs { WJob j[11]; };

__global__ void prep_all(WJobs jobs,
                         const float* __restrict__ W1, const float* __restrict__ W2,
                         float* __restrict__ wrbf,
                         float* __restrict__ agg, int nAgg4,
                         const float* __restrict__ m_input, __half* __restrict__ pm,
                         int nM8) {
    const int tid = threadIdx.x;
    const int y = blockIdx.y;
    if (y < 11) {
        WJob jb = jobs.j[y];
        const int STRb = jb.ni * 2 + 16;
        const int tot = jb.ni * jb.no;
        const int plane = jb.no * STRb;
        for (int i = blockIdx.x * 256 + tid; i < tot; i += gridDim.x * 256) {
            int k = i / jb.no, n = i % jb.no;
            float v = jb.w[i];
            __half h = __float2half_rn(v);
            __half l = __float2half_rn(v - __half2float(h));
            unsigned char* base = g_wplanes + jb.off + n * STRb + k * 2;
            *(__half*)base = h;
            *(__half*)(base + plane) = l;
        }
    } else if (y == 11) {
        float4 z = make_float4(0.f, 0.f, 0.f, 0.f);
        for (int i = blockIdx.x * 256 + tid; i < nAgg4; i += gridDim.x * 256)
            *(float4*)&agg[(size_t)i * 4] = z;
    } else if (y == 12) {
        if (blockIdx.x == 0 && tid < 128) {
            int c = tid;
            #pragma unroll
            for (int r = 0; r < 6; r++) {
                float s = 0.f;
                #pragma unroll
                for (int j = 0; j < 8; j++) s += W1[r * 8 + j] * W2[j * DD + c];
                wrbf[r * DD + c] = s;
            }
        }
    } else {
        for (int i = blockIdx.x * 256 + tid; i < nM8; i += gridDim.x * 256) {
            const float4* p = (const float4*)&m_input[(size_t)i * 8];
            float4 a = p[0], b = p[1];
            __half2 h[4];
            h[0] = __halves2half2(__float2half_rn(a.x), __float2half_rn(a.y));
            h[1] = __halves2half2(__float2half_rn(a.z), __float2half_rn(a.w));
            h[2] = __halves2half2(__float2half_rn(b.x), __float2half_rn(b.y));
            h[3] = __halves2half2(__float2half_rn(b.z), __float2half_rn(b.w));
            *(uint4*)&pm[(size_t)i * 8] = *(uint4*)h;
        }
    }
}

// ---------------------------------------------------------------------------
// sbf_proj: h[t] = sbf[t] @ W_sbf1   (42 -> 8), fp16 out. Pure stream.
// ---------------------------------------------------------------------------
#define SP_TRIP 128
__global__ __launch_bounds__(256)
void sbf_proj(const float* __restrict__ sbf, const float* __restrict__ W1,
              __half* __restrict__ hout, int Ttot) {
    __shared__ float s_sbf[SP_TRIP * 42];
    __shared__ float s_w1[42 * 8];
    const uint32_t sbs = smem_u32(s_sbf);
    const int tid = threadIdx.x;
    const int base = blockIdx.x * SP_TRIP;
    const int n_t = min(SP_TRIP, Ttot - base);

    for (int i = tid; i < 336; i += 256) s_w1[i] = W1[i];
    if (n_t == SP_TRIP) {
        const char* src = (const char*)(sbf + (size_t)base * 42);
        #pragma unroll 2
        for (int i = tid; i < SP_TRIP * 42 * 4 / 16; i += 256)
            cp_async16(sbs + i * 16, src + i * 16);
        cp_commit(); cp_wait0();
    } else {
        for (int i = tid; i < n_t * 42; i += 256) s_sbf[i] = sbf[(size_t)base * 42 + i];
    }
    __syncthreads();

    const int i = tid >> 1, j0 = (tid & 1) * 4;
    if (i < n_t) {
        float hv[4] = {0.f, 0.f, 0.f, 0.f};
        const float* row = &s_sbf[i * 42];
        #pragma unroll
        for (int k = 0; k < 42; k++) {
            float sv = row[k];
            #pragma unroll
            for (int j = 0; j < 4; j++) hv[j] += sv * s_w1[k * 8 + j0 + j];
        }
        __half2 o[2];
        o[0] = __halves2half2(__float2half_rn(hv[0]), __float2half_rn(hv[1]));
        o[1] = __halves2half2(__float2half_rn(hv[2]), __float2half_rn(hv[3]));
        *(uint2*)&hout[(size_t)(base + i) * 8 + j0] = *(uint2*)o;
    }
}

// ---------------------------------------------------------------------------
// Mega-kernel building blocks (1024 threads, 32 warps)
// ---------------------------------------------------------------------------
template <int NI>
__device__ __forceinline__ void load_act(uint32_t sb, uint32_t offA,
                                         const __half* __restrict__ src,
                                         int row0, int nrows, int tid) {
    constexpr int STR = NI * 2 + 16, NCH = NI / 8, TOT = 128 * NCH;
    #pragma unroll 2
    for (int i = tid; i < TOT; i += 1024) {
        int r = i / NCH, ch = i % NCH;
        int rr = row0 + r; if (rr >= nrows) rr = nrows - 1;
        cp_async16(sb + offA + r * STR + ch * 16, src + (size_t)rr * NI + ch * 8);
    }
}

__device__ __forceinline__ void load_w(uint32_t sb, uint32_t offW,
                                       const unsigned char* __restrict__ src,
                                       int bytes, int tid) {
    #pragma unroll 4
    for (int i = tid * 16; i < bytes; i += 1024 * 16)
        cp_async16(sb + offW + i, src + i);
}

template <int NI, int NO>
__device__ __forceinline__ void mma2(uint32_t sb, uint32_t offA, uint32_t offW,
                                     int w, int lane, float acc[NO / 32][4]) {
    constexpr int STR = NI * 2 + 16, BPL = NO * STR;
    constexpr int WN = NO / 4, NJ = WN / 8, NG = WN / 16;
    const int wm0 = (w & 7) * 16, wn0 = (w >> 3) * WN;
    const int lr = lane & 15, lk = (lane >> 4) * 8;
    #pragma unroll
    for (int nj = 0; nj < NJ; nj++)
        #pragma unroll
        for (int q = 0; q < 4; q++) acc[nj][q] = 0.f;
    #pragma unroll
    for (int k0 = 0; k0 < NI; k0 += 16) {
        uint32_t a4[4];
        ldsm_x4(a4[0], a4[1], a4[2], a4[3],
                sb + offA + (uint32_t)((wm0 + lr) * STR + (k0 + lk) * 2));
        uint32_t bh[NG][4], bl[NG][4];
        #pragma unroll
        for (int g = 0; g < NG; g++) {
            uint32_t ba = sb + offW + (uint32_t)((wn0 + g * 16 + lr) * STR + (k0 + lk) * 2);
            ldsm_x4(bh[g][0], bh[g][1], bh[g][2], bh[g][3], ba);
            ldsm_x4(bl[g][0], bl[g][1], bl[g][2], bl[g][3], ba + BPL);
        }
        #pragma unroll
        for (int nj = 0; nj < NJ; nj++)
            mma_f16(acc[nj], a4, bh[nj >> 1][nj & 1], bh[nj >> 1][(nj & 1) + 2]);
        #pragma unroll
        for (int nj = 0; nj < NJ; nj++)
            mma_f16(acc[nj], a4, bl[nj >> 1][nj & 1], bl[nj >> 1][(nj & 1) + 2]);
    }
}

// Epilogue: bias -> swish -> [gate] -> [residual] -> out.
template <int NO, bool BIAS, bool GATE, int RES, int OUT>
__device__ __forceinline__ void stage_ep2(char* smem, uint32_t offRes, uint32_t offOut,
                                          const float* __restrict__ bias,
                                          const float* __restrict__ rbf,
                                          int row0, int nrows,
                                          __half* __restrict__ yh,
                                          float* __restrict__ yf,
                                          const float* __restrict__ resf,
                                          int w, int lane, float acc[NO / 32][4]) {
    constexpr int NJ = NO / 32, WN = NO / 4;
    const int wm0 = (w & 7) * 16, wn0 = (w >> 3) * WN;
    const int sr = lane >> 2, sc = (lane & 3) * 2;
    #pragma unroll
    for (int hf = 0; hf < 2; hf++) {
        const int r = wm0 + sr + hf * 8;
        const int row = row0 + r;
        const int rc = (row < nrows) ? row : nrows - 1;
        float g6[6];
        if (GATE) {
            #pragma unroll
            for (int j = 0; j < 6; j++) g6[j] = rbf[(size_t)rc * 6 + j];
        }
        #pragma unroll
        for (int nj = 0; nj < NJ; nj++) {
            const int c = wn0 + nj * 8 + sc;
            float v0 = acc[nj][hf * 2], v1 = acc[nj][hf * 2 + 1];
            if (BIAS) { v0 += bias[c]; v1 += bias[c + 1]; }
            v0 = swishf(v0); v1 = swishf(v1);
            if (GATE) {
                float gg0 = 0.f, gg1 = 0.f;
                #pragma unroll
                for (int j = 0; j < 6; j++) {
                    gg0 += g6[j] * ((float*)smem)[j * 128 + c];
                    gg1 += g6[j] * ((float*)smem)[j * 128 + c + 1];
                }
                v0 *= gg0; v1 *= gg1;
            }
            if (RES == 1) {
                float2 f = __half22float2(*(__half2*)(smem + offRes + r * 272 + c * 2));
                v0 += f.x; v1 += f.y;
            } else if (RES == 2) {
                float2 rv = *(const float2*)&resf[(size_t)rc * NO + c];
                v0 += rv.x; v1 += rv.y;
            }
            if (OUT == 2) {
                if (row < nrows)
                    *(float2*)&yf[(size_t)row * NO + c] = make_float2(v0, v1);
            } else {
                __half2 hv = __halves2half2(__float2half_rn(v0), __float2half_rn(v1));
                if (OUT == 0)
                    *(__half2*)(smem + offOut + r * 272 + c * 2) = hv;
                else if (row < nrows)
                    *(__half2*)&yh[(size_t)row * NO + c] = hv;
            }
        }
    }
}

// ---------------------------------------------------------------------------
// mega_kj: x = swish(m@W_kj+b)*gate ; xdown = swish(x@W_down)
// ---------------------------------------------------------------------------
__global__ __launch_bounds__(1024, 1)
void mega_kj(const __half* __restrict__ pm,
             const unsigned char* __restrict__ wp,
             const float* __restrict__ b_kj, const float* __restrict__ rbf,
             const float* __restrict__ wrbf,
             __half* __restrict__ xd, int nrows) {
    extern __shared__ char smem[];
    const uint32_t sb = smem_u32(smem);
    const int tid = threadIdx.x, w = tid >> 5, lane = tid & 31;

    load_w(sb, SOFF_W0, wp + 0, PP, tid);
    load_w(sb, SOFF_W1, wp + OFF_DOWN, 34816, tid);
    cp_commit();
    for (int i = tid; i < 6 * 128; i += 1024) ((float*)smem)[i] = wrbf[i];

    float acc[4][4];
    float acc2[2][4];
    const int ntiles = (nrows + 127) >> 7;
    for (int tile = blockIdx.x; tile < ntiles; tile += gridDim.x) {
        const int row0 = tile << 7;
        load_act<128>(sb, SOFF_X, pm, row0, nrows, tid); cp_commit();
        cp_wait0(); __syncthreads();

        mma2<128, 128>(sb, SOFF_X, SOFF_W0, w, lane, acc);
        stage_ep2<128, true, true, 0, 0>(smem, 0, SOFF_T, b_kj, rbf, row0, nrows,
                                         nullptr, nullptr, nullptr, w, lane, acc);
        __syncthreads();

        mma2<128, 64>(sb, SOFF_T, SOFF_W1, w, lane, acc2);
        stage_ep2<64, false, false, 0, 1>(smem, 0, 0, nullptr, nullptr, row0, nrows,
                                          xd, nullptr, nullptr, w, lane, acc2);
    }
}

// ---------------------------------------------------------------------------
// triplet3: 16 threads per triplet, W_sbf2 slice in REGISTERS (loaded once).
// Per triplet: h uint4 broadcast, idx broadcast, xdown 8B/thread coalesced
// gather, 32 FMA, one red.add.v4 per thread. No smem in the hot path.
// ---------------------------------------------------------------------------
__global__ __launch_bounds__(256)
void triplet3(const int* __restrict__ expand, const int* __restrict__ reduce,
              const float* __restrict__ Wsbf2,
              const __half* __restrict__ hin, const __half* __restrict__ xh,
              float* __restrict__ agg, int Ttot) {
    const int tid  = threadIdx.x;
    const int lane = tid & 31;
    const int sub  = lane >> 4;          // triplet index within warp (0/1)
    const int ch   = (lane & 15) * 4;    // channel slice base

    // Per-thread W_sbf2 slice (fixed for entire kernel): 8 x float4
    float4 w2r[8];
    #pragma unroll
    for (int j = 0; j < 8; j++) w2r[j] = *(const float4*)&Wsbf2[j * 64 + ch];

    const int t = blockIdx.x * 16 + (tid >> 5) * 2 + sub;
    if (t >= Ttot) return;

    // h: 8 fp16, 16-way broadcast load
    uint4 hv4 = *(const uint4*)&hin[(size_t)t * 8];
    float h[8];
    {
        const __half2* hp = (const __half2*)&hv4;
        #pragma unroll
        for (int j = 0; j < 4; j++) {
            float2 f = __half22float2(hp[j]);
            h[2 * j] = f.x; h[2 * j + 1] = f.y;
        }
    }
    const int ekj = expand[t];
    const int eji = reduce[t];

    // xdown gather: 4 fp16 per thread (16 threads cover the 128B row)
    uint2 xv = *(const uint2*)&xh[(size_t)ekj * DAA + ch];
    float2 xa = __half22float2(((const __half2*)&xv)[0]);
    float2 xb = __half22float2(((const __half2*)&xv)[1]);

    // gate: g = h @ W_sbf2 for this thread's 4 channels
    float g0 = 0.f, g1 = 0.f, g2 = 0.f, g3 = 0.f;
    #pragma unroll
    for (int j = 0; j < 8; j++) {
        float hj = h[j];
        g0 += hj * w2r[j].x; g1 += hj * w2r[j].y;
        g2 += hj * w2r[j].z; g3 += hj * w2r[j].w;
    }

    red_add_v4(&agg[(size_t)eji * DAA + ch],
               make_float4(xa.x * g0, xa.y * g1, xb.x * g2, xb.y * g3));
}

// ---------------------------------------------------------------------------
// mega_chain: fused 9-GEMM chain; S1 reads agg fp32 directly.
// ---------------------------------------------------------------------------
__global__ __launch_bounds__(1024, 1)
void mega_chain(const float* __restrict__ aggf, const __half* __restrict__ pm,
                const unsigned char* __restrict__ wp,
                const float* __restrict__ b_ji, const float* __restrict__ b_res_b,
                const float* __restrict__ b_final, const float* __restrict__ b_res_a,
                const float* __restrict__ m_input, float* __restrict__ out,
                int nrows) {
    extern __shared__ char smem[];
    const uint32_t sb = smem_u32(smem);
    const int tid = threadIdx.x, w = tid >> 5, lane = tid & 31;
    float acc[4][4];

    uint32_t wA = SOFF_W0, wB = SOFF_W1;
    load_w(sb, wA, wp + OFF_UP, 36864, tid); cp_commit();

    const int ntiles = (nrows + 127) >> 7;
    for (int tile = blockIdx.x; tile < ntiles; tile += gridDim.x) {
        const int row0 = tile << 7;

        // agg fp32 -> fp16 smem X (STR=144)
        {
            int r = tid >> 3, c0 = (tid & 7) * 8;
            int rr = row0 + r; if (rr >= nrows) rr = nrows - 1;
            float4 a = *(const float4*)&aggf[(size_t)rr * DAA + c0];
            float4 b = *(const float4*)&aggf[(size_t)rr * DAA + c0 + 4];
            __half2 hh[4];
            hh[0] = __halves2half2(__float2half_rn(a.x), __float2half_rn(a.y));
            hh[1] = __halves2half2(__float2half_rn(a.z), __float2half_rn(a.w));
            hh[2] = __halves2half2(__float2half_rn(b.x), __float2half_rn(b.y));
            hh[3] = __halves2half2(__float2half_rn(b.z), __float2half_rn(b.w));
            *(uint4*)(smem + SOFF_X + r * 144 + c0 * 2) = *(uint4*)hh;
        }
        cp_wait0(); __syncthreads();

        // S1: p = swish(agg @ W_up)
        mma2<64, 128>(sb, SOFF_X, wA, w, lane, acc);
        __syncthreads();
        load_act<128>(sb, SOFF_X, pm, row0, nrows, tid);
        load_w(sb, wB, wp + 1 * PP, PP, tid); cp_commit();
        stage_ep2<128, false, false, 0, 0>(smem, 0, SOFF_T, nullptr, nullptr, row0, nrows,
                                           nullptr, nullptr, nullptr, w, lane, acc);
        cp_wait0(); __syncthreads(); { uint32_t t = wA; wA = wB; wB = t; }

        // S2: m1 = swish(m@W_ji+b) + p
        mma2<128, 128>(sb, SOFF_X, wA, w, lane, acc);
        load_w(sb, wB, wp + 2 * PP, PP, tid); cp_commit();
        stage_ep2<128, true, false, 1, 0>(smem, SOFF_T, SOFF_T, b_ji, nullptr, row0, nrows,
                                          nullptr, nullptr, nullptr, w, lane, acc);
        cp_wait0(); __syncthreads(); { uint32_t t = wA; wA = wB; wB = t; }

        // S3: t = swish(m1@Wb0+b)
        mma2<128, 128>(sb, SOFF_T, wA, w, lane, acc);
        load_w(sb, wB, wp + 3 * PP, PP, tid); cp_commit();
        stage_ep2<128, true, false, 0, 0>(smem, 0, SOFF_X, b_res_b, nullptr, row0, nrows,
                                          nullptr, nullptr, nullptr, w, lane, acc);
        cp_wait0(); __syncthreads(); { uint32_t t = wA; wA = wB; wB = t; }

        // S4: m2 = m1 + swish(t@Wb1+b)
        mma2<128, 128>(sb, SOFF_X, wA, w, lane, acc);
        load_w(sb, wB, wp + 4 * PP, PP, tid); cp_commit();
        stage_ep2<128, true, false, 1, 0>(smem, SOFF_T, SOFF_T, b_res_b + DD, nullptr, row0, nrows,
                                          nullptr, nullptr, nullptr, w, lane, acc);
        cp_wait0(); __syncthreads(); { uint32_t t = wA; wA = wB; wB = t; }

        // S5: m3 = swish(m2@W_final+b) + m_input
        mma2<128, 128>(sb, SOFF_T, wA, w, lane, acc);
        load_w(sb, wB, wp + 5 * PP, PP, tid); cp_commit();
        stage_ep2<128, true, false, 2, 0>(smem, 0, SOFF_X, b_final, nullptr, row0, nrows,
                                          nullptr, nullptr, m_input, w, lane, acc);
        cp_wait0(); __syncthreads(); { uint32_t t = wA; wA = wB; wB = t; }

        // S6: t = swish(m3@Wa00+b)
        mma2<128, 128>(sb, SOFF_X, wA, w, lane, acc);
        load_w(sb, wB, wp + 6 * PP, PP, tid); cp_commit();
        stage_ep2<128, true, false, 0, 0>(smem, 0, SOFF_T, b_res_a, nullptr, row0, nrows,
                                          nullptr, nullptr, nullptr, w, lane, acc);
        cp_wait0(); __syncthreads(); { uint32_t t = wA; wA = wB; wB = t; }

        // S7: m4 = m3 + swish(t@Wa01+b)
        mma2<128, 128>(sb, SOFF_T, wA, w, lane, acc);
        load_w(sb, wB, wp + 7 * PP, PP, tid); cp_commit();
        stage_ep2<128, true, false, 1, 0>(smem, SOFF_X, SOFF_X, b_res_a + DD, nullptr, row0, nrows,
                                          nullptr, nullptr, nullptr, w, lane, acc);
        cp_wait0(); __syncthreads(); { uint32_t t = wA; wA = wB; wB = t; }

        // S8: t = swish(m4@Wa10+b)
        mma2<128, 128>(sb, SOFF_X, wA, w, lane, acc);
        load_w(sb, wB, wp + 8 * PP, PP, tid); cp_commit();
        stage_ep2<128, true, false, 0, 0>(smem, 0, SOFF_T, b_res_a + 2 * DD, nullptr, row0, nrows,
                                          nullptr, nullptr, nullptr, w, lane, acc);
        cp_wait0(); __syncthreads(); { uint32_t t = wA; wA = wB; wB = t; }

        // S9: out = m4 + swish(t@Wa11+b)  -> gmem fp32
        mma2<128, 128>(sb, SOFF_T, wA, w, lane, acc);
        load_w(sb, wB, wp + OFF_UP, 36864, tid); cp_commit();
        stage_ep2<128, true, false, 1, 2>(smem, SOFF_X, 0, b_res_a + 3 * DD, nullptr, row0, nrows,
                                          nullptr, out, nullptr, w, lane, acc);
        cp_wait0(); __syncthreads(); { uint32_t t = wA; wA = wB; wB = t; }
    }
}

// ---------------------------------------------------------------------------
// Host launcher
// ---------------------------------------------------------------------------
extern "C" void kernel_launch(void* const* d_in, const int* in_sizes, int n_in,
                              void* d_out, int out_size) {
    const float* m_input = (const float*)d_in[0];
    const float* rbf     = (const float*)d_in[1];
    const float* sbf     = (const float*)d_in[2];
    const int*   expand  = (const int*)d_in[3];
    const int*   reduce  = (const int*)d_in[4];
    const float* W_kj    = (const float*)d_in[5];
    const float* b_kj    = (const float*)d_in[6];
    const float* W_rbf1  = (const float*)d_in[7];
    const float* W_rbf2  = (const float*)d_in[8];
    const float* W_sbf1  = (const float*)d_in[9];
    const float* W_sbf2  = (const float*)d_in[10];
    const float* W_down  = (const float*)d_in[11];
    const float* W_up    = (const float*)d_in[12];
    const float* W_ji    = (const float*)d_in[13];
    const float* b_ji    = (const float*)d_in[14];
    const float* W_res_b = (const float*)d_in[15];
    const float* b_res_b = (const float*)d_in[16];
    const float* W_final = (const float*)d_in[17];
    const float* b_final = (const float*)d_in[18];
    const float* W_res_a = (const float*)d_in[19];
    const float* b_res_a = (const float*)d_in[20];
    float* out = (float*)d_out;

    const int E = in_sizes[0] / DD;
    const int T = in_sizes[3];

    unsigned char *pm, *pxd, *ph, *wp;
    float *agg, *wrbf;
    cudaGetSymbolAddress((void**)&pm,  g_pm);
    cudaGetSymbolAddress((void**)&pxd, g_pxd);
    cudaGetSymbolAddress((void**)&ph,  g_h);
    cudaGetSymbolAddress((void**)&agg, g_agg);
    cudaGetSymbolAddress((void**)&wrbf, g_wrbf);
    cudaGetSymbolAddress((void**)&wp,  g_wplanes);

    __half* pm_h  = (__half*)pm;
    __half* pxd_h = (__half*)pxd;
    __half* h_buf = (__half*)ph;

    int smcnt = 148, dev = 0;
    cudaGetDevice(&dev);
    cudaDeviceGetAttribute(&smcnt, cudaDevAttrMultiProcessorCount, dev);
    const int ntiles = (E + 127) / 128;
    const int grid = (ntiles < smcnt) ? ntiles : smcnt;

    cudaFuncSetAttribute(mega_kj,    cudaFuncAttributeMaxDynamicSharedMemorySize, SMEM_MEGA);
    cudaFuncSetAttribute(mega_chain, cudaFuncAttributeMaxDynamicSharedMemorySize, SMEM_MEGA);

    // 1) all preprocessing in one kernel
    {
        WJobs jobs;
        jobs.j[0]  = {W_kj,            128, 128, 0 * PP};
        jobs.j[1]  = {W_ji,            128, 128, 1 * PP};
        jobs.j[2]  = {W_res_b,         128, 128, 2 * PP};
        jobs.j[3]  = {W_res_b + 16384, 128, 128, 3 * PP};
        jobs.j[4]  = {W_final,         128, 128, 4 * PP};
        jobs.j[5]  = {W_res_a,         128, 128, 5 * PP};
        jobs.j[6]  = {W_res_a + 16384, 128, 128, 6 * PP};
        jobs.j[7]  = {W_res_a + 32768, 128, 128, 7 * PP};
        jobs.j[8]  = {W_res_a + 49152, 128, 128, 8 * PP};
        jobs.j[9]  = {W_down,          128, 64,  OFF_DOWN};
        jobs.j[10] = {W_up,            64,  128, OFF_UP};
        dim3 g(256, 14);
        prep_all<<<g, 256>>>(jobs, W_rbf1, W_rbf2, wrbf,
                             agg, E * DAA / 4, m_input, pm_h, E * DD / 8);
    }
    // 2) h = sbf @ W_sbf1 (fp16)
    sbf_proj<<<(T + SP_TRIP - 1) / SP_TRIP, 256>>>(sbf, W_sbf1, h_buf, T);
    // 3) fused kj+gate+down
    mega_kj<<<grid, 1024, SMEM_MEGA>>>(pm_h, wp, b_kj, rbf, wrbf, pxd_h, E);
    // 4) triplet gather/gate/scatter (register-resident W_sbf2)
    triplet3<<<(T + 15) / 16, 256>>>(expand, reduce, W_sbf2, h_buf, pxd_h, agg, T);
    // 5) fused 9-GEMM chain -> out
    mega_chain<<<grid, 1024, SMEM_MEGA>>>(agg, pm_h, wp,
                                          b_ji, b_res_b, b_final, b_res_a,
                                          m_input, out, E);
}